// round 1
// baseline (speedup 1.0000x reference)
#include <cuda_runtime.h>
#include <math.h>

#define Bn   4
#define CINn 256
#define Fn   128
#define Nn   4096
#define EPSc 1e-5f

// ---------------- scratch (device globals: no allocation allowed) ----------
__device__ float d_proj[(size_t)3 * Bn * Fn * Nn];   // [proj][b][f][n], proj: 0=g,1=theta,2=phi
__device__ float d_y[(size_t)Bn * Fn * Nn];          // attention output [b][f][n]
__device__ float d_z[(size_t)Bn * CINn * Nn];        // pre-LN output     [b][c][n]
__device__ float d_part[2 * Bn * 256];               // per-block (sum,sumsq) partials
__device__ float d_stats[2 * Bn];                    // per-batch (mu, rsig)

// ---------------- kernel 1: the three 1x1-conv GEMMs -----------------------
// out[f][n] = sum_c W[f][c] * x[b][c][n] + bias[f];  M=128, K=256, N=4096
__global__ __launch_bounds__(256) void proj_kernel(
    const float* __restrict__ x,
    const float* __restrict__ Wg, const float* __restrict__ bg,
    const float* __restrict__ Wt, const float* __restrict__ bt,
    const float* __restrict__ Wp, const float* __restrict__ bp)
{
    int pb   = blockIdx.z;          // 0..11
    int proj = pb % 3;
    int b    = pb / 3;
    const float* Wm; const float* bias;
    if (proj == 0)      { Wm = Wg; bias = bg; }
    else if (proj == 1) { Wm = Wt; bias = bt; }
    else                { Wm = Wp; bias = bp; }

    const float* X  = x + (size_t)b * CINn * Nn;
    float* out = d_proj + ((size_t)proj * Bn + b) * Fn * Nn;

    int m0 = blockIdx.y * 64;
    int n0 = blockIdx.x * 64;

    __shared__ float As[16][64];   // As[k][m] = W[m0+m][k0+k]
    __shared__ float Bs[16][64];   // Bs[k][n] = X[k0+k][n0+n]

    int tid = threadIdx.x;
    int tx = tid & 15, ty = tid >> 4;

    float acc[4][4];
    #pragma unroll
    for (int i = 0; i < 4; i++)
        #pragma unroll
        for (int j = 0; j < 4; j++) acc[i][j] = 0.f;

    for (int k0 = 0; k0 < CINn; k0 += 16) {
        #pragma unroll
        for (int i = 0; i < 4; i++) {
            int e = tid + i * 256;
            int k = e & 15, m = e >> 4;
            As[k][m] = Wm[(size_t)(m0 + m) * CINn + k0 + k];
        }
        #pragma unroll
        for (int i = 0; i < 4; i++) {
            int e = tid + i * 256;
            int n = e & 63, k = e >> 6;
            Bs[k][n] = X[(size_t)(k0 + k) * Nn + n0 + n];
        }
        __syncthreads();
        #pragma unroll
        for (int k = 0; k < 16; k++) {
            float4 a = *(const float4*)&As[k][ty * 4];
            float4 c = *(const float4*)&Bs[k][tx * 4];
            float av[4] = {a.x, a.y, a.z, a.w};
            float bw[4] = {c.x, c.y, c.z, c.w};
            #pragma unroll
            for (int i = 0; i < 4; i++)
                #pragma unroll
                for (int j = 0; j < 4; j++)
                    acc[i][j] += av[i] * bw[j];
        }
        __syncthreads();
    }

    #pragma unroll
    for (int i = 0; i < 4; i++) {
        float bi = bias[m0 + ty * 4 + i];
        float4 v = make_float4(acc[i][0] + bi, acc[i][1] + bi,
                               acc[i][2] + bi, acc[i][3] + bi);
        *(float4*)&out[(size_t)(m0 + ty * 4 + i) * Nn + n0 + tx * 4] = v;
    }
}

// ---------------- kernel 2: fused flash-style attention --------------------
struct AttnSmem {
    float Th[Fn][64];       // theta block  [k][q]   (reused as O staging at end)
    float Ph[Fn][64];       // phi chunk    [k][m]
    float Gt[64][Fn + 4];   // g chunk transposed [m][f] (padded)
    float Ps[64][68];       // scores / probabilities [q][m] (padded)
    float red[4][64];
    float mrow[64];
    float lrow[64];
    float arow[64];
};

__global__ __launch_bounds__(256, 1) void attn_kernel()
{
    extern __shared__ char smraw[];
    AttnSmem& sm = *reinterpret_cast<AttnSmem*>(smraw);

    int b  = blockIdx.y;
    int q0 = blockIdx.x * 64;
    const float* g  = d_proj + ((size_t)0 * Bn + b) * Fn * Nn;
    const float* th = d_proj + ((size_t)1 * Bn + b) * Fn * Nn;
    const float* ph = d_proj + ((size_t)2 * Bn + b) * Fn * Nn;

    int tid  = threadIdx.x;
    int tx   = tid & 15, ty = tid >> 4;
    int qrow = tid & 63, part = tid >> 6;

    for (int e = tid; e < Fn * 64; e += 256) {
        int q = e & 63, k = e >> 6;
        sm.Th[k][q] = th[(size_t)k * Nn + q0 + q];
    }
    if (tid < 64) { sm.mrow[tid] = -3.0e38f; sm.lrow[tid] = 0.f; }

    float acc[4][8];
    #pragma unroll
    for (int i = 0; i < 4; i++)
        #pragma unroll
        for (int j = 0; j < 8; j++) acc[i][j] = 0.f;

    __syncthreads();

    for (int m0 = 0; m0 < Nn; m0 += 64) {
        // load key/value chunk
        for (int e = tid; e < Fn * 64; e += 256) {
            int n = e & 63, k = e >> 6;
            sm.Ph[k][n] = ph[(size_t)k * Nn + m0 + n];
            sm.Gt[n][k] = g[(size_t)k * Nn + m0 + n];
        }
        __syncthreads();

        // S[q][m] = sum_k Th[k][q] * Ph[k][m]
        float s[4][4];
        #pragma unroll
        for (int i = 0; i < 4; i++)
            #pragma unroll
            for (int j = 0; j < 4; j++) s[i][j] = 0.f;

        #pragma unroll 8
        for (int k = 0; k < Fn; k++) {
            float4 a = *(const float4*)&sm.Th[k][ty * 4];
            float4 c = *(const float4*)&sm.Ph[k][tx * 4];
            float av[4] = {a.x, a.y, a.z, a.w};
            float bw[4] = {c.x, c.y, c.z, c.w};
            #pragma unroll
            for (int i = 0; i < 4; i++)
                #pragma unroll
                for (int j = 0; j < 4; j++)
                    s[i][j] += av[i] * bw[j];
        }
        #pragma unroll
        for (int i = 0; i < 4; i++)
            *(float4*)&sm.Ps[ty * 4 + i][tx * 4] =
                make_float4(s[i][0], s[i][1], s[i][2], s[i][3]);
        __syncthreads();

        // online softmax: row max
        float lmax = -3.0e38f;
        #pragma unroll
        for (int j = 0; j < 16; j++)
            lmax = fmaxf(lmax, sm.Ps[qrow][part * 16 + j]);
        sm.red[part][qrow] = lmax;
        __syncthreads();
        if (tid < 64) {
            float nm = fmaxf(fmaxf(sm.red[0][tid], sm.red[1][tid]),
                             fmaxf(sm.red[2][tid], sm.red[3][tid]));
            nm = fmaxf(nm, sm.mrow[tid]);
            sm.arow[tid] = __expf(sm.mrow[tid] - nm);
            sm.mrow[tid] = nm;
        }
        __syncthreads();

        // exponentiate + row sums
        float nm = sm.mrow[qrow];
        float lsum = 0.f;
        #pragma unroll
        for (int j = 0; j < 16; j++) {
            float p = __expf(sm.Ps[qrow][part * 16 + j] - nm);
            sm.Ps[qrow][part * 16 + j] = p;
            lsum += p;
        }
        sm.red[part][qrow] = lsum;
        __syncthreads();
        if (tid < 64) {
            sm.lrow[tid] = sm.lrow[tid] * sm.arow[tid] +
                sm.red[0][tid] + sm.red[1][tid] + sm.red[2][tid] + sm.red[3][tid];
        }

        // rescale accumulator + O += P @ G^T
        float al[4];
        #pragma unroll
        for (int i = 0; i < 4; i++) al[i] = sm.arow[ty * 4 + i];
        #pragma unroll
        for (int i = 0; i < 4; i++)
            #pragma unroll
            for (int j = 0; j < 8; j++) acc[i][j] *= al[i];

        #pragma unroll 4
        for (int m = 0; m < 64; m++) {
            float4 g0 = *(const float4*)&sm.Gt[m][tx * 8];
            float4 g1 = *(const float4*)&sm.Gt[m][tx * 8 + 4];
            float gv[8] = {g0.x, g0.y, g0.z, g0.w, g1.x, g1.y, g1.z, g1.w};
            float pv[4] = {sm.Ps[ty * 4 + 0][m], sm.Ps[ty * 4 + 1][m],
                           sm.Ps[ty * 4 + 2][m], sm.Ps[ty * 4 + 3][m]};
            #pragma unroll
            for (int i = 0; i < 4; i++)
                #pragma unroll
                for (int j = 0; j < 8; j++)
                    acc[i][j] += pv[i] * gv[j];
        }
        __syncthreads();
    }

    // normalize and stage for coalesced store (overlay on Gt region, pitch 65)
    float linv[4];
    #pragma unroll
    for (int i = 0; i < 4; i++) linv[i] = 1.0f / sm.lrow[ty * 4 + i];

    float* Os = &sm.Gt[0][0];   // needs 128*65 = 8320 floats <= 64*132 = 8448
    #pragma unroll
    for (int i = 0; i < 4; i++)
        #pragma unroll
        for (int j = 0; j < 8; j++)
            Os[(size_t)(tx * 8 + j) * 65 + (ty * 4 + i)] = acc[i][j] * linv[i];
    __syncthreads();

    float* yb = d_y + (size_t)b * Fn * Nn;
    for (int e = tid; e < Fn * 64; e += 256) {
        int q = e & 63, k = e >> 6;
        yb[(size_t)k * Nn + q0 + q] = Os[(size_t)k * 65 + q];
    }
}

// ---------------- kernel 3: z = Wz @ y + bz, with per-tile LN partials -----
__global__ __launch_bounds__(256) void zgemm_kernel(
    const float* __restrict__ Wz, const float* __restrict__ bz)
{
    int b  = blockIdx.z;
    int m0 = blockIdx.y * 64;
    int n0 = blockIdx.x * 64;
    const float* Y = d_y + (size_t)b * Fn * Nn;
    float* Z = d_z + (size_t)b * CINn * Nn;

    __shared__ float As[16][64];
    __shared__ float Bs[16][64];
    __shared__ float rs[256], rq[256];

    int tid = threadIdx.x;
    int tx = tid & 15, ty = tid >> 4;

    float acc[4][4];
    #pragma unroll
    for (int i = 0; i < 4; i++)
        #pragma unroll
        for (int j = 0; j < 4; j++) acc[i][j] = 0.f;

    for (int k0 = 0; k0 < Fn; k0 += 16) {
        #pragma unroll
        for (int i = 0; i < 4; i++) {
            int e = tid + i * 256;
            int k = e & 15, m = e >> 4;
            As[k][m] = Wz[(size_t)(m0 + m) * Fn + k0 + k];
        }
        #pragma unroll
        for (int i = 0; i < 4; i++) {
            int e = tid + i * 256;
            int n = e & 63, k = e >> 6;
            Bs[k][n] = Y[(size_t)(k0 + k) * Nn + n0 + n];
        }
        __syncthreads();
        #pragma unroll
        for (int k = 0; k < 16; k++) {
            float4 a = *(const float4*)&As[k][ty * 4];
            float4 c = *(const float4*)&Bs[k][tx * 4];
            float av[4] = {a.x, a.y, a.z, a.w};
            float bw[4] = {c.x, c.y, c.z, c.w};
            #pragma unroll
            for (int i = 0; i < 4; i++)
                #pragma unroll
                for (int j = 0; j < 4; j++)
                    acc[i][j] += av[i] * bw[j];
        }
        __syncthreads();
    }

    float lsum = 0.f, lsq = 0.f;
    #pragma unroll
    for (int i = 0; i < 4; i++) {
        float bi = bz[m0 + ty * 4 + i];
        float v0 = acc[i][0] + bi, v1 = acc[i][1] + bi;
        float v2 = acc[i][2] + bi, v3 = acc[i][3] + bi;
        *(float4*)&Z[(size_t)(m0 + ty * 4 + i) * Nn + n0 + tx * 4] =
            make_float4(v0, v1, v2, v3);
        lsum += v0 + v1 + v2 + v3;
        lsq  += v0 * v0 + v1 * v1 + v2 * v2 + v3 * v3;
    }
    rs[tid] = lsum; rq[tid] = lsq;
    __syncthreads();
    #pragma unroll
    for (int s = 128; s > 0; s >>= 1) {
        if (tid < s) { rs[tid] += rs[tid + s]; rq[tid] += rq[tid + s]; }
        __syncthreads();
    }
    if (tid == 0) {
        int idx = b * 256 + blockIdx.y * 64 + blockIdx.x;
        d_part[2 * idx]     = rs[0];
        d_part[2 * idx + 1] = rq[0];
    }
}

// ---------------- kernel 4: per-batch mean / rsig ---------------------------
__global__ __launch_bounds__(256) void stats_kernel()
{
    int b = blockIdx.x;
    int tid = threadIdx.x;
    __shared__ float rs[256], rq[256];
    int idx = b * 256 + tid;
    rs[tid] = d_part[2 * idx];
    rq[tid] = d_part[2 * idx + 1];
    __syncthreads();
    #pragma unroll
    for (int s = 128; s > 0; s >>= 1) {
        if (tid < s) { rs[tid] += rs[tid + s]; rq[tid] += rq[tid + s]; }
        __syncthreads();
    }
    if (tid == 0) {
        float inv = 1.0f / ((float)CINn * (float)Nn);
        float mu  = rs[0] * inv;
        float var = rq[0] * inv - mu * mu;
        d_stats[2 * b]     = mu;
        d_stats[2 * b + 1] = rsqrtf(var + EPSc);
    }
}

// ---------------- kernel 5: LN affine + residual ----------------------------
__global__ __launch_bounds__(256) void finalize_kernel(
    const float* __restrict__ x, const float* __restrict__ lw,
    const float* __restrict__ lb, float* __restrict__ out)
{
    const int per_b4 = CINn * Nn / 4;
    const int tot4   = Bn * per_b4;
    for (int i = blockIdx.x * blockDim.x + threadIdx.x; i < tot4;
         i += gridDim.x * blockDim.x) {
        int b = i / per_b4;
        int r = i - b * per_b4;
        float mu   = d_stats[2 * b];
        float rsig = d_stats[2 * b + 1];
        float4 z  = ((const float4*)d_z)[i];
        float4 xv = ((const float4*)x)[i];
        float4 w  = ((const float4*)lw)[r];
        float4 bb = ((const float4*)lb)[r];
        float4 o;
        o.x = (z.x - mu) * rsig * w.x + bb.x + xv.x;
        o.y = (z.y - mu) * rsig * w.y + bb.y + xv.y;
        o.z = (z.z - mu) * rsig * w.z + bb.z + xv.z;
        o.w = (z.w - mu) * rsig * w.w + bb.w + xv.w;
        ((float4*)out)[i] = o;
    }
}

// ---------------- launch -----------------------------------------------------
extern "C" void kernel_launch(void* const* d_in, const int* in_sizes, int n_in,
                              void* d_out, int out_size)
{
    const float* x   = (const float*)d_in[0];
    const float* Wg  = (const float*)d_in[1];
    const float* bg  = (const float*)d_in[2];
    const float* Wt  = (const float*)d_in[3];
    const float* bt  = (const float*)d_in[4];
    const float* Wp  = (const float*)d_in[5];
    const float* bp  = (const float*)d_in[6];
    const float* Wz  = (const float*)d_in[7];
    const float* bz  = (const float*)d_in[8];
    const float* lnw = (const float*)d_in[9];
    const float* lnb = (const float*)d_in[10];
    float* out = (float*)d_out;

    cudaFuncSetAttribute(attn_kernel, cudaFuncAttributeMaxDynamicSharedMemorySize,
                         (int)sizeof(AttnSmem));

    proj_kernel<<<dim3(64, 2, 12), 256>>>(x, Wg, bg, Wt, bt, Wp, bp);
    attn_kernel<<<dim3(64, 4), 256, sizeof(AttnSmem)>>>();
    zgemm_kernel<<<dim3(64, 4, 4), 256>>>(Wz, bz);
    stats_kernel<<<4, 256>>>();
    finalize_kernel<<<4096, 256>>>(x, lnw, lnb, out);
}

// round 2
// speedup vs baseline: 2.9596x; 2.9596x over previous
#include <cuda_runtime.h>
#include <math.h>
#include <stdint.h>

#define Bn   4
#define CINn 256
#define Fn   128
#define Nn   4096
#define EPSc 1e-5f

// ---------------- scratch (device globals: no allocation allowed) ----------
__device__ float d_proj[(size_t)3 * Bn * Fn * Nn];   // [proj][b][f][n], 0=g,1=theta,2=phi
__device__ float d_y[(size_t)Bn * Fn * Nn];          // attention output [b][f][n]
__device__ float d_z[(size_t)Bn * CINn * Nn];        // pre-LN output    [b][c][n]
__device__ float d_part[2 * Bn * 256];               // per-block (sum,sumsq) partials
__device__ float d_stats[2 * Bn];                    // per-batch (mu, rsig)

// ---------------- tf32 helpers ---------------------------------------------
__device__ __forceinline__ uint32_t f2tf(float f) {
    uint32_t r;
    asm("cvt.rna.tf32.f32 %0, %1;" : "=r"(r) : "f"(f));
    return r;
}
__device__ __forceinline__ void mma8(float c[4],
        uint32_t a0, uint32_t a1, uint32_t a2, uint32_t a3,
        uint32_t b0, uint32_t b1) {
    asm volatile(
        "mma.sync.aligned.m16n8k8.row.col.f32.tf32.tf32.f32 "
        "{%0,%1,%2,%3}, {%4,%5,%6,%7}, {%8,%9}, {%0,%1,%2,%3};\n"
        : "+f"(c[0]), "+f"(c[1]), "+f"(c[2]), "+f"(c[3])
        : "r"(a0), "r"(a1), "r"(a2), "r"(a3), "r"(b0), "r"(b1));
}
__device__ __forceinline__ uint32_t fbits(float f) { return __float_as_uint(f); }

// ---------------- kernel 1: the three 1x1-conv GEMMs (fp32 FFMA) -----------
__global__ __launch_bounds__(256) void proj_kernel(
    const float* __restrict__ x,
    const float* __restrict__ Wg, const float* __restrict__ bg,
    const float* __restrict__ Wt, const float* __restrict__ bt,
    const float* __restrict__ Wp, const float* __restrict__ bp)
{
    int pb   = blockIdx.z;
    int proj = pb % 3;
    int b    = pb / 3;
    const float* Wm; const float* bias;
    if (proj == 0)      { Wm = Wg; bias = bg; }
    else if (proj == 1) { Wm = Wt; bias = bt; }
    else                { Wm = Wp; bias = bp; }

    const float* X  = x + (size_t)b * CINn * Nn;
    float* out = d_proj + ((size_t)proj * Bn + b) * Fn * Nn;

    int m0 = blockIdx.y * 64;
    int n0 = blockIdx.x * 64;

    __shared__ float As[16][64];
    __shared__ float Bs[16][64];

    int tid = threadIdx.x;
    int tx = tid & 15, ty = tid >> 4;

    float acc[4][4];
    #pragma unroll
    for (int i = 0; i < 4; i++)
        #pragma unroll
        for (int j = 0; j < 4; j++) acc[i][j] = 0.f;

    for (int k0 = 0; k0 < CINn; k0 += 16) {
        #pragma unroll
        for (int i = 0; i < 4; i++) {
            int e = tid + i * 256;
            int k = e & 15, m = e >> 4;
            As[k][m] = Wm[(size_t)(m0 + m) * CINn + k0 + k];
        }
        #pragma unroll
        for (int i = 0; i < 4; i++) {
            int e = tid + i * 256;
            int n = e & 63, k = e >> 6;
            Bs[k][n] = X[(size_t)(k0 + k) * Nn + n0 + n];
        }
        __syncthreads();
        #pragma unroll
        for (int k = 0; k < 16; k++) {
            float4 a = *(const float4*)&As[k][ty * 4];
            float4 c = *(const float4*)&Bs[k][tx * 4];
            float av[4] = {a.x, a.y, a.z, a.w};
            float bw[4] = {c.x, c.y, c.z, c.w};
            #pragma unroll
            for (int i = 0; i < 4; i++)
                #pragma unroll
                for (int j = 0; j < 4; j++)
                    acc[i][j] += av[i] * bw[j];
        }
        __syncthreads();
    }

    #pragma unroll
    for (int i = 0; i < 4; i++) {
        float bi = bias[m0 + ty * 4 + i];
        float4 v = make_float4(acc[i][0] + bi, acc[i][1] + bi,
                               acc[i][2] + bi, acc[i][3] + bi);
        *(float4*)&out[(size_t)(m0 + ty * 4 + i) * Nn + n0 + tx * 4] = v;
    }
}

// ---------------- kernel 2: fused flash attention on tf32 mma.sync ---------
// q-block 128 (grid 32x4 = 128 CTAs, single wave). 8 warps, each owns 16 q-rows:
// softmax state (running max / sum) lives in registers, reduced via shfl over
// the 4-lane column group. Per 64-key chunk: S = theta^T phi (m16n8k8 x128),
// online softmax, O += P G^T (x128).  All fragment LDS are conflict-free
// (pitches = 8 mod 32).
struct ASmem {
    float Th[Fn][136];   // theta  [k][q],  q-block 128   (reused as O staging)
    float Ph[Fn][72];    // phi    [k][m],  chunk 64
    float Gs[Fn][72];    // g      [k][m],  chunk 64
    float Ps[128][72];   // probs  [q][m]
};

__global__ __launch_bounds__(256, 1) void attn_kernel()
{
    extern __shared__ char smraw[];
    ASmem& sm = *reinterpret_cast<ASmem*>(smraw);

    int b  = blockIdx.y;
    int q0 = blockIdx.x * 128;
    const float* g  = d_proj + ((size_t)0 * Bn + b) * Fn * Nn;
    const float* th = d_proj + ((size_t)1 * Bn + b) * Fn * Nn;
    const float* ph = d_proj + ((size_t)2 * Bn + b) * Fn * Nn;

    int tid  = threadIdx.x;
    int lane = tid & 31, warp = tid >> 5;
    int r = lane >> 2, cl = lane & 3;
    int qrow = warp * 16 + r;            // rows qrow (c0,c1) and qrow+8 (c2,c3)

    // ---- load theta (tf32) into Th[k][q], vectorized ----
    for (int e = tid; e < Fn * 128 / 4; e += 256) {
        int k = e >> 5, q4 = (e & 31) * 4;
        float4 v = *(const float4*)&th[(size_t)k * Nn + q0 + q4];
        float4 t = make_float4(__uint_as_float(f2tf(v.x)), __uint_as_float(f2tf(v.y)),
                               __uint_as_float(f2tf(v.z)), __uint_as_float(f2tf(v.w)));
        *(float4*)&sm.Th[k][q4] = t;
    }

    float oc[16][4];
    #pragma unroll
    for (int i = 0; i < 16; i++)
        #pragma unroll
        for (int j = 0; j < 4; j++) oc[i][j] = 0.f;

    float m0_ = -3.0e38f, m1_ = -3.0e38f;   // running row max (rows qrow, qrow+8)
    float l0_ = 0.f,      l1_ = 0.f;        // running row sum

    __syncthreads();

    for (int mb = 0; mb < Nn; mb += 64) {
        // ---- load phi + g chunk (tf32) ----
        for (int e = tid; e < Fn * 64 / 4; e += 256) {
            int k = e >> 4, n4 = (e & 15) * 4;
            float4 v = *(const float4*)&ph[(size_t)k * Nn + mb + n4];
            float4 t = make_float4(__uint_as_float(f2tf(v.x)), __uint_as_float(f2tf(v.y)),
                                   __uint_as_float(f2tf(v.z)), __uint_as_float(f2tf(v.w)));
            *(float4*)&sm.Ph[k][n4] = t;
            float4 w = *(const float4*)&g[(size_t)k * Nn + mb + n4];
            float4 u = make_float4(__uint_as_float(f2tf(w.x)), __uint_as_float(f2tf(w.y)),
                                   __uint_as_float(f2tf(w.z)), __uint_as_float(f2tf(w.w)));
            *(float4*)&sm.Gs[k][n4] = u;
        }
        __syncthreads();

        // ---- S = theta^T phi : warp computes 16q x 64m ----
        float sc[8][4];
        #pragma unroll
        for (int i = 0; i < 8; i++)
            #pragma unroll
            for (int j = 0; j < 4; j++) sc[i][j] = 0.f;

        #pragma unroll
        for (int kk = 0; kk < Fn; kk += 8) {
            uint32_t a0 = fbits(sm.Th[kk + cl    ][qrow    ]);
            uint32_t a1 = fbits(sm.Th[kk + cl    ][qrow + 8]);
            uint32_t a2 = fbits(sm.Th[kk + cl + 4][qrow    ]);
            uint32_t a3 = fbits(sm.Th[kk + cl + 4][qrow + 8]);
            #pragma unroll
            for (int nt = 0; nt < 8; nt++) {
                int mc = nt * 8 + r;
                uint32_t b0 = fbits(sm.Ph[kk + cl    ][mc]);
                uint32_t b1 = fbits(sm.Ph[kk + cl + 4][mc]);
                mma8(sc[nt], a0, a1, a2, a3, b0, b1);
            }
        }

        // ---- online softmax (warp-local) ----
        float mx0 = -3.0e38f, mx1 = -3.0e38f;
        #pragma unroll
        for (int nt = 0; nt < 8; nt++) {
            mx0 = fmaxf(mx0, fmaxf(sc[nt][0], sc[nt][1]));
            mx1 = fmaxf(mx1, fmaxf(sc[nt][2], sc[nt][3]));
        }
        #pragma unroll
        for (int o = 1; o < 4; o <<= 1) {
            mx0 = fmaxf(mx0, __shfl_xor_sync(0xffffffffu, mx0, o));
            mx1 = fmaxf(mx1, __shfl_xor_sync(0xffffffffu, mx1, o));
        }
        float nm0 = fmaxf(m0_, mx0), nm1 = fmaxf(m1_, mx1);
        float al0 = __expf(m0_ - nm0), al1 = __expf(m1_ - nm1);
        m0_ = nm0; m1_ = nm1;

        float rs0 = 0.f, rs1 = 0.f;
        #pragma unroll
        for (int nt = 0; nt < 8; nt++) {
            float p0 = __expf(sc[nt][0] - nm0);
            float p1 = __expf(sc[nt][1] - nm0);
            float p2 = __expf(sc[nt][2] - nm1);
            float p3 = __expf(sc[nt][3] - nm1);
            rs0 += p0 + p1; rs1 += p2 + p3;
            int mc = nt * 8 + 2 * cl;
            sm.Ps[qrow    ][mc    ] = __uint_as_float(f2tf(p0));
            sm.Ps[qrow    ][mc + 1] = __uint_as_float(f2tf(p1));
            sm.Ps[qrow + 8][mc    ] = __uint_as_float(f2tf(p2));
            sm.Ps[qrow + 8][mc + 1] = __uint_as_float(f2tf(p3));
        }
        #pragma unroll
        for (int o = 1; o < 4; o <<= 1) {
            rs0 += __shfl_xor_sync(0xffffffffu, rs0, o);
            rs1 += __shfl_xor_sync(0xffffffffu, rs1, o);
        }
        l0_ = l0_ * al0 + rs0;
        l1_ = l1_ * al1 + rs1;

        // rescale O accumulators
        #pragma unroll
        for (int ft = 0; ft < 16; ft++) {
            oc[ft][0] *= al0; oc[ft][1] *= al0;
            oc[ft][2] *= al1; oc[ft][3] *= al1;
        }

        __syncwarp();   // Ps written by this warp, read below by this warp

        // ---- O += P G^T : warp computes 16q x 128f ----
        #pragma unroll
        for (int mk = 0; mk < 64; mk += 8) {
            uint32_t a0 = fbits(sm.Ps[qrow    ][mk + cl    ]);
            uint32_t a1 = fbits(sm.Ps[qrow + 8][mk + cl    ]);
            uint32_t a2 = fbits(sm.Ps[qrow    ][mk + cl + 4]);
            uint32_t a3 = fbits(sm.Ps[qrow + 8][mk + cl + 4]);
            #pragma unroll
            for (int ft = 0; ft < 16; ft++) {
                int fb = ft * 8 + r;
                uint32_t b0 = fbits(sm.Gs[fb][mk + cl    ]);
                uint32_t b1 = fbits(sm.Gs[fb][mk + cl + 4]);
                mma8(oc[ft], a0, a1, a2, a3, b0, b1);
            }
        }
        __syncthreads();   // Ph/Gs consumed; safe to overwrite next chunk
    }

    // ---- epilogue: normalize, stage [f][q] in Th region, coalesced store ----
    float li0 = 1.0f / l0_, li1 = 1.0f / l1_;
    float* Os = &sm.Th[0][0];   // pitch 136
    #pragma unroll
    for (int ft = 0; ft < 16; ft++) {
        int fb = ft * 8 + 2 * cl;
        Os[(size_t)(fb    ) * 136 + qrow    ] = oc[ft][0] * li0;
        Os[(size_t)(fb + 1) * 136 + qrow    ] = oc[ft][1] * li0;
        Os[(size_t)(fb    ) * 136 + qrow + 8] = oc[ft][2] * li1;
        Os[(size_t)(fb + 1) * 136 + qrow + 8] = oc[ft][3] * li1;
    }
    __syncthreads();

    float* yb = d_y + (size_t)b * Fn * Nn;
    for (int e = tid; e < Fn * 128 / 4; e += 256) {
        int k = e >> 5, q4 = (e & 31) * 4;
        float4 v = *(const float4*)&Os[(size_t)k * 136 + q4];
        *(float4*)&yb[(size_t)k * Nn + q0 + q4] = v;
    }
}

// ---------------- kernel 3: z = Wz @ y + bz, with per-tile LN partials -----
__global__ __launch_bounds__(256) void zgemm_kernel(
    const float* __restrict__ Wz, const float* __restrict__ bz)
{
    int b  = blockIdx.z;
    int m0 = blockIdx.y * 64;
    int n0 = blockIdx.x * 64;
    const float* Y = d_y + (size_t)b * Fn * Nn;
    float* Z = d_z + (size_t)b * CINn * Nn;

    __shared__ float As[16][64];
    __shared__ float Bs[16][64];
    __shared__ float rs[256], rq[256];

    int tid = threadIdx.x;
    int tx = tid & 15, ty = tid >> 4;

    float acc[4][4];
    #pragma unroll
    for (int i = 0; i < 4; i++)
        #pragma unroll
        for (int j = 0; j < 4; j++) acc[i][j] = 0.f;

    for (int k0 = 0; k0 < Fn; k0 += 16) {
        #pragma unroll
        for (int i = 0; i < 4; i++) {
            int e = tid + i * 256;
            int k = e & 15, m = e >> 4;
            As[k][m] = Wz[(size_t)(m0 + m) * Fn + k0 + k];
        }
        #pragma unroll
        for (int i = 0; i < 4; i++) {
            int e = tid + i * 256;
            int n = e & 63, k = e >> 6;
            Bs[k][n] = Y[(size_t)(k0 + k) * Nn + n0 + n];
        }
        __syncthreads();
        #pragma unroll
        for (int k = 0; k < 16; k++) {
            float4 a = *(const float4*)&As[k][ty * 4];
            float4 c = *(const float4*)&Bs[k][tx * 4];
            float av[4] = {a.x, a.y, a.z, a.w};
            float bw[4] = {c.x, c.y, c.z, c.w};
            #pragma unroll
            for (int i = 0; i < 4; i++)
                #pragma unroll
                for (int j = 0; j < 4; j++)
                    acc[i][j] += av[i] * bw[j];
        }
        __syncthreads();
    }

    float lsum = 0.f, lsq = 0.f;
    #pragma unroll
    for (int i = 0; i < 4; i++) {
        float bi = bz[m0 + ty * 4 + i];
        float v0 = acc[i][0] + bi, v1 = acc[i][1] + bi;
        float v2 = acc[i][2] + bi, v3 = acc[i][3] + bi;
        *(float4*)&Z[(size_t)(m0 + ty * 4 + i) * Nn + n0 + tx * 4] =
            make_float4(v0, v1, v2, v3);
        lsum += v0 + v1 + v2 + v3;
        lsq  += v0 * v0 + v1 * v1 + v2 * v2 + v3 * v3;
    }
    rs[tid] = lsum; rq[tid] = lsq;
    __syncthreads();
    #pragma unroll
    for (int s = 128; s > 0; s >>= 1) {
        if (tid < s) { rs[tid] += rs[tid + s]; rq[tid] += rq[tid + s]; }
        __syncthreads();
    }
    if (tid == 0) {
        int idx = b * 256 + blockIdx.y * 64 + blockIdx.x;
        d_part[2 * idx]     = rs[0];
        d_part[2 * idx + 1] = rq[0];
    }
}

// ---------------- kernel 4: per-batch mean / rsig ---------------------------
__global__ __launch_bounds__(256) void stats_kernel()
{
    int b = blockIdx.x;
    int tid = threadIdx.x;
    __shared__ float rs[256], rq[256];
    int idx = b * 256 + tid;
    rs[tid] = d_part[2 * idx];
    rq[tid] = d_part[2 * idx + 1];
    __syncthreads();
    #pragma unroll
    for (int s = 128; s > 0; s >>= 1) {
        if (tid < s) { rs[tid] += rs[tid + s]; rq[tid] += rq[tid + s]; }
        __syncthreads();
    }
    if (tid == 0) {
        float inv = 1.0f / ((float)CINn * (float)Nn);
        float mu  = rs[0] * inv;
        float var = rq[0] * inv - mu * mu;
        d_stats[2 * b]     = mu;
        d_stats[2 * b + 1] = rsqrtf(var + EPSc);
    }
}

// ---------------- kernel 5: LN affine + residual ----------------------------
__global__ __launch_bounds__(256) void finalize_kernel(
    const float* __restrict__ x, const float* __restrict__ lw,
    const float* __restrict__ lb, float* __restrict__ out)
{
    const int per_b4 = CINn * Nn / 4;
    const int tot4   = Bn * per_b4;
    for (int i = blockIdx.x * blockDim.x + threadIdx.x; i < tot4;
         i += gridDim.x * blockDim.x) {
        int b = i / per_b4;
        int r = i - b * per_b4;
        float mu   = d_stats[2 * b];
        float rsig = d_stats[2 * b + 1];
        float4 z  = ((const float4*)d_z)[i];
        float4 xv = ((const float4*)x)[i];
        float4 w  = ((const float4*)lw)[r];
        float4 bb = ((const float4*)lb)[r];
        float4 o;
        o.x = (z.x - mu) * rsig * w.x + bb.x + xv.x;
        o.y = (z.y - mu) * rsig * w.y + bb.y + xv.y;
        o.z = (z.z - mu) * rsig * w.z + bb.z + xv.z;
        o.w = (z.w - mu) * rsig * w.w + bb.w + xv.w;
        ((float4*)out)[i] = o;
    }
}

// ---------------- launch -----------------------------------------------------
extern "C" void kernel_launch(void* const* d_in, const int* in_sizes, int n_in,
                              void* d_out, int out_size)
{
    const float* x   = (const float*)d_in[0];
    const float* Wg  = (const float*)d_in[1];
    const float* bg  = (const float*)d_in[2];
    const float* Wt  = (const float*)d_in[3];
    const float* bt  = (const float*)d_in[4];
    const float* Wp  = (const float*)d_in[5];
    const float* bp  = (const float*)d_in[6];
    const float* Wz  = (const float*)d_in[7];
    const float* bz  = (const float*)d_in[8];
    const float* lnw = (const float*)d_in[9];
    const float* lnb = (const float*)d_in[10];
    float* out = (float*)d_out;

    cudaFuncSetAttribute(attn_kernel, cudaFuncAttributeMaxDynamicSharedMemorySize,
                         (int)sizeof(ASmem));

    proj_kernel<<<dim3(64, 2, 12), 256>>>(x, Wg, bg, Wt, bt, Wp, bp);
    attn_kernel<<<dim3(32, 4), 256, sizeof(ASmem)>>>();
    zgemm_kernel<<<dim3(64, 4, 4), 256>>>(Wz, bz);
    stats_kernel<<<4, 256>>>();
    finalize_kernel<<<4096, 256>>>(x, lnw, lnb, out);
}

// round 3
// speedup vs baseline: 3.7964x; 1.2828x over previous
#include <cuda_runtime.h>
#include <math.h>
#include <stdint.h>

#define Bn   4
#define CINn 256
#define Fn   128
#define Nn   4096
#define EPSc 1e-5f

// ---------------- scratch (device globals: no allocation allowed) ----------
__device__ float d_proj[(size_t)3 * Bn * Fn * Nn];   // [proj][b][f][n], 0=g,1=theta,2=phi
__device__ float d_y[(size_t)Bn * Fn * Nn];          // attention output [b][f][n]
__device__ float d_z[(size_t)Bn * CINn * Nn];        // pre-LN output    [b][c][n]
__device__ float d_part[2 * Bn * 128];               // per-tile (sum,sumsq) partials
__device__ float d_stats[2 * Bn];                    // per-batch (mu, rsig)

// ---------------- tf32 helpers ---------------------------------------------
__device__ __forceinline__ uint32_t f2tf(float f) {
    uint32_t r;
    asm("cvt.rna.tf32.f32 %0, %1;" : "=r"(r) : "f"(f));
    return r;
}
__device__ __forceinline__ float4 tf4(float4 v) {
    return make_float4(__uint_as_float(f2tf(v.x)), __uint_as_float(f2tf(v.y)),
                       __uint_as_float(f2tf(v.z)), __uint_as_float(f2tf(v.w)));
}
__device__ __forceinline__ void mma8(float c[4],
        uint32_t a0, uint32_t a1, uint32_t a2, uint32_t a3,
        uint32_t b0, uint32_t b1) {
    asm volatile(
        "mma.sync.aligned.m16n8k8.row.col.f32.tf32.tf32.f32 "
        "{%0,%1,%2,%3}, {%4,%5,%6,%7}, {%8,%9}, {%0,%1,%2,%3};\n"
        : "+f"(c[0]), "+f"(c[1]), "+f"(c[2]), "+f"(c[3])
        : "r"(a0), "r"(a1), "r"(a2), "r"(a3), "r"(b0), "r"(b1));
}
__device__ __forceinline__ uint32_t fbits(float f) { return __float_as_uint(f); }

// ============================================================================
// kernel 1: the three 1x1-conv GEMMs on tf32 mma
//   out[m][n] = sum_k W[m][k] * X[k][n] + bias[m];  M=128, K=256, N=4096
//   8 warps x 16 m-rows, n-tile 64, K chunked by 64.
//   Ws pitch 68 (A frag LDS conflict-free), Xs pitch 72 (B frag conflict-free)
// ============================================================================
#define WS_PITCH 68
#define XS_PITCH 72
#define GEMM_SMEM ((128 * WS_PITCH + 64 * XS_PITCH) * 4)

__global__ __launch_bounds__(256) void proj_mma(
    const float* __restrict__ x,
    const float* __restrict__ Wg, const float* __restrict__ bg,
    const float* __restrict__ Wt, const float* __restrict__ bt,
    const float* __restrict__ Wp, const float* __restrict__ bp)
{
    extern __shared__ float smem[];
    float* Ws = smem;                 // [128][68]
    float* Xs = smem + 128 * WS_PITCH; // [64][72]

    int pb   = blockIdx.y;
    int proj = pb % 3;
    int b    = pb / 3;
    const float* Wm; const float* bias;
    if (proj == 0)      { Wm = Wg; bias = bg; }
    else if (proj == 1) { Wm = Wt; bias = bt; }
    else                { Wm = Wp; bias = bp; }

    const float* X = x + (size_t)b * CINn * Nn;
    float* out = d_proj + ((size_t)proj * Bn + b) * Fn * Nn;
    int n0 = blockIdx.x * 64;

    int tid = threadIdx.x;
    int lane = tid & 31, warp = tid >> 5;
    int r = lane >> 2, cl = lane & 3;
    int qrow = warp * 16 + r;

    float acc[8][4];
    #pragma unroll
    for (int i = 0; i < 8; i++)
        #pragma unroll
        for (int j = 0; j < 4; j++) acc[i][j] = 0.f;

    for (int kc = 0; kc < CINn; kc += 64) {
        // W chunk: [128][64] -> Ws[m][k]
        #pragma unroll
        for (int e = tid; e < 128 * 16; e += 256) {
            int m = e >> 4, k4 = (e & 15) * 4;
            float4 v = tf4(*(const float4*)&Wm[(size_t)m * CINn + kc + k4]);
            *(float4*)&Ws[m * WS_PITCH + k4] = v;
        }
        // X chunk: [64][64] -> Xs[k][n]
        #pragma unroll
        for (int e = tid; e < 64 * 16; e += 256) {
            int k = e >> 4, n4 = (e & 15) * 4;
            float4 v = tf4(*(const float4*)&X[(size_t)(kc + k) * Nn + n0 + n4]);
            *(float4*)&Xs[k * XS_PITCH + n4] = v;
        }
        __syncthreads();

        #pragma unroll
        for (int kk = 0; kk < 64; kk += 8) {
            uint32_t a0 = fbits(Ws[qrow       * WS_PITCH + kk + cl    ]);
            uint32_t a1 = fbits(Ws[(qrow + 8) * WS_PITCH + kk + cl    ]);
            uint32_t a2 = fbits(Ws[qrow       * WS_PITCH + kk + cl + 4]);
            uint32_t a3 = fbits(Ws[(qrow + 8) * WS_PITCH + kk + cl + 4]);
            #pragma unroll
            for (int nt = 0; nt < 8; nt++) {
                int mc = nt * 8 + r;
                uint32_t b0 = fbits(Xs[(kk + cl)     * XS_PITCH + mc]);
                uint32_t b1 = fbits(Xs[(kk + cl + 4) * XS_PITCH + mc]);
                mma8(acc[nt], a0, a1, a2, a3, b0, b1);
            }
        }
        __syncthreads();
    }

    float bi0 = bias[qrow], bi1 = bias[qrow + 8];
    #pragma unroll
    for (int nt = 0; nt < 8; nt++) {
        int nc = n0 + nt * 8 + 2 * cl;
        *(float2*)&out[(size_t)qrow * Nn + nc] =
            make_float2(acc[nt][0] + bi0, acc[nt][1] + bi0);
        *(float2*)&out[(size_t)(qrow + 8) * Nn + nc] =
            make_float2(acc[nt][2] + bi1, acc[nt][3] + bi1);
    }
}

// ============================================================================
// kernel 2: fused flash attention on tf32 mma.sync  (unchanged from R2)
// ============================================================================
struct ASmem {
    float Th[Fn][136];   // theta  [k][q],  q-block 128   (reused as O staging)
    float Ph[Fn][72];    // phi    [k][m],  chunk 64
    float Gs[Fn][72];    // g      [k][m],  chunk 64
    float Ps[128][72];   // probs  [q][m]
};

__global__ __launch_bounds__(256, 1) void attn_kernel()
{
    extern __shared__ char smraw[];
    ASmem& sm = *reinterpret_cast<ASmem*>(smraw);

    int b  = blockIdx.y;
    int q0 = blockIdx.x * 128;
    const float* g  = d_proj + ((size_t)0 * Bn + b) * Fn * Nn;
    const float* th = d_proj + ((size_t)1 * Bn + b) * Fn * Nn;
    const float* ph = d_proj + ((size_t)2 * Bn + b) * Fn * Nn;

    int tid  = threadIdx.x;
    int lane = tid & 31, warp = tid >> 5;
    int r = lane >> 2, cl = lane & 3;
    int qrow = warp * 16 + r;

    for (int e = tid; e < Fn * 128 / 4; e += 256) {
        int k = e >> 5, q4 = (e & 31) * 4;
        float4 v = tf4(*(const float4*)&th[(size_t)k * Nn + q0 + q4]);
        *(float4*)&sm.Th[k][q4] = v;
    }

    float oc[16][4];
    #pragma unroll
    for (int i = 0; i < 16; i++)
        #pragma unroll
        for (int j = 0; j < 4; j++) oc[i][j] = 0.f;

    float m0_ = -3.0e38f, m1_ = -3.0e38f;
    float l0_ = 0.f,      l1_ = 0.f;

    __syncthreads();

    for (int mb = 0; mb < Nn; mb += 64) {
        for (int e = tid; e < Fn * 64 / 4; e += 256) {
            int k = e >> 4, n4 = (e & 15) * 4;
            float4 t = tf4(*(const float4*)&ph[(size_t)k * Nn + mb + n4]);
            *(float4*)&sm.Ph[k][n4] = t;
            float4 u = tf4(*(const float4*)&g[(size_t)k * Nn + mb + n4]);
            *(float4*)&sm.Gs[k][n4] = u;
        }
        __syncthreads();

        float sc[8][4];
        #pragma unroll
        for (int i = 0; i < 8; i++)
            #pragma unroll
            for (int j = 0; j < 4; j++) sc[i][j] = 0.f;

        #pragma unroll
        for (int kk = 0; kk < Fn; kk += 8) {
            uint32_t a0 = fbits(sm.Th[kk + cl    ][qrow    ]);
            uint32_t a1 = fbits(sm.Th[kk + cl    ][qrow + 8]);
            uint32_t a2 = fbits(sm.Th[kk + cl + 4][qrow    ]);
            uint32_t a3 = fbits(sm.Th[kk + cl + 4][qrow + 8]);
            #pragma unroll
            for (int nt = 0; nt < 8; nt++) {
                int mc = nt * 8 + r;
                uint32_t b0 = fbits(sm.Ph[kk + cl    ][mc]);
                uint32_t b1 = fbits(sm.Ph[kk + cl + 4][mc]);
                mma8(sc[nt], a0, a1, a2, a3, b0, b1);
            }
        }

        float mx0 = -3.0e38f, mx1 = -3.0e38f;
        #pragma unroll
        for (int nt = 0; nt < 8; nt++) {
            mx0 = fmaxf(mx0, fmaxf(sc[nt][0], sc[nt][1]));
            mx1 = fmaxf(mx1, fmaxf(sc[nt][2], sc[nt][3]));
        }
        #pragma unroll
        for (int o = 1; o < 4; o <<= 1) {
            mx0 = fmaxf(mx0, __shfl_xor_sync(0xffffffffu, mx0, o));
            mx1 = fmaxf(mx1, __shfl_xor_sync(0xffffffffu, mx1, o));
        }
        float nm0 = fmaxf(m0_, mx0), nm1 = fmaxf(m1_, mx1);
        float al0 = __expf(m0_ - nm0), al1 = __expf(m1_ - nm1);
        m0_ = nm0; m1_ = nm1;

        float rs0 = 0.f, rs1 = 0.f;
        #pragma unroll
        for (int nt = 0; nt < 8; nt++) {
            float p0 = __expf(sc[nt][0] - nm0);
            float p1 = __expf(sc[nt][1] - nm0);
            float p2 = __expf(sc[nt][2] - nm1);
            float p3 = __expf(sc[nt][3] - nm1);
            rs0 += p0 + p1; rs1 += p2 + p3;
            int mc = nt * 8 + 2 * cl;
            sm.Ps[qrow    ][mc    ] = __uint_as_float(f2tf(p0));
            sm.Ps[qrow    ][mc + 1] = __uint_as_float(f2tf(p1));
            sm.Ps[qrow + 8][mc    ] = __uint_as_float(f2tf(p2));
            sm.Ps[qrow + 8][mc + 1] = __uint_as_float(f2tf(p3));
        }
        #pragma unroll
        for (int o = 1; o < 4; o <<= 1) {
            rs0 += __shfl_xor_sync(0xffffffffu, rs0, o);
            rs1 += __shfl_xor_sync(0xffffffffu, rs1, o);
        }
        l0_ = l0_ * al0 + rs0;
        l1_ = l1_ * al1 + rs1;

        #pragma unroll
        for (int ft = 0; ft < 16; ft++) {
            oc[ft][0] *= al0; oc[ft][1] *= al0;
            oc[ft][2] *= al1; oc[ft][3] *= al1;
        }

        __syncwarp();

        #pragma unroll
        for (int mk = 0; mk < 64; mk += 8) {
            uint32_t a0 = fbits(sm.Ps[qrow    ][mk + cl    ]);
            uint32_t a1 = fbits(sm.Ps[qrow + 8][mk + cl    ]);
            uint32_t a2 = fbits(sm.Ps[qrow    ][mk + cl + 4]);
            uint32_t a3 = fbits(sm.Ps[qrow + 8][mk + cl + 4]);
            #pragma unroll
            for (int ft = 0; ft < 16; ft++) {
                int fb = ft * 8 + r;
                uint32_t b0 = fbits(sm.Gs[fb][mk + cl    ]);
                uint32_t b1 = fbits(sm.Gs[fb][mk + cl + 4]);
                mma8(oc[ft], a0, a1, a2, a3, b0, b1);
            }
        }
        __syncthreads();
    }

    float li0 = 1.0f / l0_, li1 = 1.0f / l1_;
    float* Os = &sm.Th[0][0];   // pitch 136
    #pragma unroll
    for (int ft = 0; ft < 16; ft++) {
        int fb = ft * 8 + 2 * cl;
        Os[(size_t)(fb    ) * 136 + qrow    ] = oc[ft][0] * li0;
        Os[(size_t)(fb + 1) * 136 + qrow    ] = oc[ft][1] * li0;
        Os[(size_t)(fb    ) * 136 + qrow + 8] = oc[ft][2] * li1;
        Os[(size_t)(fb + 1) * 136 + qrow + 8] = oc[ft][3] * li1;
    }
    __syncthreads();

    float* yb = d_y + (size_t)b * Fn * Nn;
    for (int e = tid; e < Fn * 128 / 4; e += 256) {
        int k = e >> 5, q4 = (e & 31) * 4;
        float4 v = *(const float4*)&Os[(size_t)k * 136 + q4];
        *(float4*)&yb[(size_t)k * Nn + q0 + q4] = v;
    }
}

// ============================================================================
// kernel 3: z = Wz @ y + bz on tf32 mma, with per-tile LN partials
//   M=256 (m-tile 128 via grid.y), K=128, N=4096
// ============================================================================
__global__ __launch_bounds__(256) void zgemm_mma(
    const float* __restrict__ Wz, const float* __restrict__ bz)
{
    extern __shared__ float smem[];
    float* Ws = smem;
    float* Xs = smem + 128 * WS_PITCH;

    int b  = blockIdx.z;
    int m0 = blockIdx.y * 128;
    int n0 = blockIdx.x * 64;
    const float* Y = d_y + (size_t)b * Fn * Nn;
    float* Z = d_z + (size_t)b * CINn * Nn;

    int tid = threadIdx.x;
    int lane = tid & 31, warp = tid >> 5;
    int r = lane >> 2, cl = lane & 3;
    int qrow = warp * 16 + r;

    float acc[8][4];
    #pragma unroll
    for (int i = 0; i < 8; i++)
        #pragma unroll
        for (int j = 0; j < 4; j++) acc[i][j] = 0.f;

    for (int kc = 0; kc < Fn; kc += 64) {
        #pragma unroll
        for (int e = tid; e < 128 * 16; e += 256) {
            int m = e >> 4, k4 = (e & 15) * 4;
            float4 v = tf4(*(const float4*)&Wz[(size_t)(m0 + m) * Fn + kc + k4]);
            *(float4*)&Ws[m * WS_PITCH + k4] = v;
        }
        #pragma unroll
        for (int e = tid; e < 64 * 16; e += 256) {
            int k = e >> 4, n4 = (e & 15) * 4;
            float4 v = tf4(*(const float4*)&Y[(size_t)(kc + k) * Nn + n0 + n4]);
            *(float4*)&Xs[k * XS_PITCH + n4] = v;
        }
        __syncthreads();

        #pragma unroll
        for (int kk = 0; kk < 64; kk += 8) {
            uint32_t a0 = fbits(Ws[qrow       * WS_PITCH + kk + cl    ]);
            uint32_t a1 = fbits(Ws[(qrow + 8) * WS_PITCH + kk + cl    ]);
            uint32_t a2 = fbits(Ws[qrow       * WS_PITCH + kk + cl + 4]);
            uint32_t a3 = fbits(Ws[(qrow + 8) * WS_PITCH + kk + cl + 4]);
            #pragma unroll
            for (int nt = 0; nt < 8; nt++) {
                int mc = nt * 8 + r;
                uint32_t b0 = fbits(Xs[(kk + cl)     * XS_PITCH + mc]);
                uint32_t b1 = fbits(Xs[(kk + cl + 4) * XS_PITCH + mc]);
                mma8(acc[nt], a0, a1, a2, a3, b0, b1);
            }
        }
        __syncthreads();
    }

    float bi0 = bz[m0 + qrow], bi1 = bz[m0 + qrow + 8];
    float lsum = 0.f, lsq = 0.f;
    #pragma unroll
    for (int nt = 0; nt < 8; nt++) {
        int nc = n0 + nt * 8 + 2 * cl;
        float v0 = acc[nt][0] + bi0, v1 = acc[nt][1] + bi0;
        float v2 = acc[nt][2] + bi1, v3 = acc[nt][3] + bi1;
        *(float2*)&Z[(size_t)(m0 + qrow) * Nn + nc]     = make_float2(v0, v1);
        *(float2*)&Z[(size_t)(m0 + qrow + 8) * Nn + nc] = make_float2(v2, v3);
        lsum += v0 + v1 + v2 + v3;
        lsq  += v0 * v0 + v1 * v1 + v2 * v2 + v3 * v3;
    }

    // block reduction of (sum, sumsq) -> d_part
    float* rs = smem;         // reuse (all mma reads complete)
    float* rq = smem + 256;
    rs[tid] = lsum; rq[tid] = lsq;
    __syncthreads();
    #pragma unroll
    for (int s = 128; s > 0; s >>= 1) {
        if (tid < s) { rs[tid] += rs[tid + s]; rq[tid] += rq[tid + s]; }
        __syncthreads();
    }
    if (tid == 0) {
        int idx = b * 128 + blockIdx.y * 64 + blockIdx.x;
        d_part[2 * idx]     = rs[0];
        d_part[2 * idx + 1] = rq[0];
    }
}

// ---------------- kernel 4: per-batch mean / rsig ---------------------------
__global__ __launch_bounds__(128) void stats_kernel()
{
    int b = blockIdx.x;
    int tid = threadIdx.x;
    __shared__ float rs[128], rq[128];
    int idx = b * 128 + tid;
    rs[tid] = d_part[2 * idx];
    rq[tid] = d_part[2 * idx + 1];
    __syncthreads();
    #pragma unroll
    for (int s = 64; s > 0; s >>= 1) {
        if (tid < s) { rs[tid] += rs[tid + s]; rq[tid] += rq[tid + s]; }
        __syncthreads();
    }
    if (tid == 0) {
        float inv = 1.0f / ((float)CINn * (float)Nn);
        float mu  = rs[0] * inv;
        float var = rq[0] * inv - mu * mu;
        d_stats[2 * b]     = mu;
        d_stats[2 * b + 1] = rsqrtf(var + EPSc);
    }
}

// ---------------- kernel 5: LN affine + residual ----------------------------
__global__ __launch_bounds__(256) void finalize_kernel(
    const float* __restrict__ x, const float* __restrict__ lw,
    const float* __restrict__ lb, float* __restrict__ out)
{
    const int per_b4 = CINn * Nn / 4;
    const int tot4   = Bn * per_b4;
    for (int i = blockIdx.x * blockDim.x + threadIdx.x; i < tot4;
         i += gridDim.x * blockDim.x) {
        int b = i / per_b4;
        int r = i - b * per_b4;
        float mu   = d_stats[2 * b];
        float rsig = d_stats[2 * b + 1];
        float4 z  = ((const float4*)d_z)[i];
        float4 xv = ((const float4*)x)[i];
        float4 w  = ((const float4*)lw)[r];
        float4 bb = ((const float4*)lb)[r];
        float4 o;
        o.x = (z.x - mu) * rsig * w.x + bb.x + xv.x;
        o.y = (z.y - mu) * rsig * w.y + bb.y + xv.y;
        o.z = (z.z - mu) * rsig * w.z + bb.z + xv.z;
        o.w = (z.w - mu) * rsig * w.w + bb.w + xv.w;
        ((float4*)out)[i] = o;
    }
}

// ---------------- launch -----------------------------------------------------
extern "C" void kernel_launch(void* const* d_in, const int* in_sizes, int n_in,
                              void* d_out, int out_size)
{
    const float* x   = (const float*)d_in[0];
    const float* Wg  = (const float*)d_in[1];
    const float* bg  = (const float*)d_in[2];
    const float* Wt  = (const float*)d_in[3];
    const float* bt  = (const float*)d_in[4];
    const float* Wp  = (const float*)d_in[5];
    const float* bp  = (const float*)d_in[6];
    const float* Wz  = (const float*)d_in[7];
    const float* bz  = (const float*)d_in[8];
    const float* lnw = (const float*)d_in[9];
    const float* lnb = (const float*)d_in[10];
    float* out = (float*)d_out;

    cudaFuncSetAttribute(attn_kernel, cudaFuncAttributeMaxDynamicSharedMemorySize,
                         (int)sizeof(ASmem));
    cudaFuncSetAttribute(proj_mma, cudaFuncAttributeMaxDynamicSharedMemorySize,
                         GEMM_SMEM);
    cudaFuncSetAttribute(zgemm_mma, cudaFuncAttributeMaxDynamicSharedMemorySize,
                         GEMM_SMEM);

    proj_mma<<<dim3(64, 12), 256, GEMM_SMEM>>>(x, Wg, bg, Wt, bt, Wp, bp);
    attn_kernel<<<dim3(32, 4), 256, sizeof(ASmem)>>>();
    zgemm_mma<<<dim3(64, 2, 4), 256, GEMM_SMEM>>>(Wz, bz);
    stats_kernel<<<4, 128>>>();
    finalize_kernel<<<4096, 256>>>(x, lnw, lnb, out);
}

// round 4
// speedup vs baseline: 3.7981x; 1.0004x over previous
#include <cuda_runtime.h>
#include <math.h>
#include <stdint.h>

#define Bn   4
#define CINn 256
#define Fn   128
#define Nn   4096
#define EPSc 1e-5f

// ---------------- scratch (device globals: no allocation allowed) ----------
__device__ float d_proj[(size_t)3 * Bn * Fn * Nn];   // [proj][b][f][n], 0=g,1=theta,2=phi
__device__ float d_y[(size_t)Bn * Fn * Nn];          // attention output [b][f][n]
__device__ float d_z[(size_t)Bn * CINn * Nn];        // pre-LN output    [b][c][n]
__device__ float d_part[2 * Bn * 128];               // per-tile (sum,sumsq) partials
__device__ float d_stats[2 * Bn];                    // per-batch (mu, rsig)

// ---------------- tf32 helpers ---------------------------------------------
__device__ __forceinline__ uint32_t f2tf(float f) {
    uint32_t r;
    asm("cvt.rna.tf32.f32 %0, %1;" : "=r"(r) : "f"(f));
    return r;
}
__device__ __forceinline__ float4 tf4(float4 v) {
    return make_float4(__uint_as_float(f2tf(v.x)), __uint_as_float(f2tf(v.y)),
                       __uint_as_float(f2tf(v.z)), __uint_as_float(f2tf(v.w)));
}
__device__ __forceinline__ void mma8(float c[4],
        uint32_t a0, uint32_t a1, uint32_t a2, uint32_t a3,
        uint32_t b0, uint32_t b1) {
    asm volatile(
        "mma.sync.aligned.m16n8k8.row.col.f32.tf32.tf32.f32 "
        "{%0,%1,%2,%3}, {%4,%5,%6,%7}, {%8,%9}, {%0,%1,%2,%3};\n"
        : "+f"(c[0]), "+f"(c[1]), "+f"(c[2]), "+f"(c[3])
        : "r"(a0), "r"(a1), "r"(a2), "r"(a3), "r"(b0), "r"(b1));
}
__device__ __forceinline__ uint32_t fbits(float f) { return __float_as_uint(f); }

// ============================================================================
// kernel 1: the three 1x1-conv GEMMs on tf32 mma
//   out[m][n] = sum_k W[m][k] * X[k][n] + bias[m];  M=128, K=256, N=4096
//   8 warps x 16 m-rows, n-tile 64, K chunked by 64.
//   Ws pitch 68 (A frag LDS conflict-free), Xs pitch 72 (B frag conflict-free)
// ============================================================================
#define WS_PITCH 68
#define XS_PITCH 72
#define GEMM_SMEM ((128 * WS_PITCH + 64 * XS_PITCH) * 4)

__global__ __launch_bounds__(256) void proj_mma(
    const float* __restrict__ x,
    const float* __restrict__ Wg, const float* __restrict__ bg,
    const float* __restrict__ Wt, const float* __restrict__ bt,
    const float* __restrict__ Wp, const float* __restrict__ bp)
{
    extern __shared__ float smem[];
    float* Ws = smem;                 // [128][68]
    float* Xs = smem + 128 * WS_PITCH; // [64][72]

    int pb   = blockIdx.y;
    int proj = pb % 3;
    int b    = pb / 3;
    const float* Wm; const float* bias;
    if (proj == 0)      { Wm = Wg; bias = bg; }
    else if (proj == 1) { Wm = Wt; bias = bt; }
    else                { Wm = Wp; bias = bp; }

    const float* X = x + (size_t)b * CINn * Nn;
    float* out = d_proj + ((size_t)proj * Bn + b) * Fn * Nn;
    int n0 = blockIdx.x * 64;

    int tid = threadIdx.x;
    int lane = tid & 31, warp = tid >> 5;
    int r = lane >> 2, cl = lane & 3;
    int qrow = warp * 16 + r;

    float acc[8][4];
    #pragma unroll
    for (int i = 0; i < 8; i++)
        #pragma unroll
        for (int j = 0; j < 4; j++) acc[i][j] = 0.f;

    for (int kc = 0; kc < CINn; kc += 64) {
        // W chunk: [128][64] -> Ws[m][k]
        #pragma unroll
        for (int e = tid; e < 128 * 16; e += 256) {
            int m = e >> 4, k4 = (e & 15) * 4;
            float4 v = tf4(*(const float4*)&Wm[(size_t)m * CINn + kc + k4]);
            *(float4*)&Ws[m * WS_PITCH + k4] = v;
        }
        // X chunk: [64][64] -> Xs[k][n]
        #pragma unroll
        for (int e = tid; e < 64 * 16; e += 256) {
            int k = e >> 4, n4 = (e & 15) * 4;
            float4 v = tf4(*(const float4*)&X[(size_t)(kc + k) * Nn + n0 + n4]);
            *(float4*)&Xs[k * XS_PITCH + n4] = v;
        }
        __syncthreads();

        #pragma unroll
        for (int kk = 0; kk < 64; kk += 8) {
            uint32_t a0 = fbits(Ws[qrow       * WS_PITCH + kk + cl    ]);
            uint32_t a1 = fbits(Ws[(qrow + 8) * WS_PITCH + kk + cl    ]);
            uint32_t a2 = fbits(Ws[qrow       * WS_PITCH + kk + cl + 4]);
            uint32_t a3 = fbits(Ws[(qrow + 8) * WS_PITCH + kk + cl + 4]);
            #pragma unroll
            for (int nt = 0; nt < 8; nt++) {
                int mc = nt * 8 + r;
                uint32_t b0 = fbits(Xs[(kk + cl)     * XS_PITCH + mc]);
                uint32_t b1 = fbits(Xs[(kk + cl + 4) * XS_PITCH + mc]);
                mma8(acc[nt], a0, a1, a2, a3, b0, b1);
            }
        }
        __syncthreads();
    }

    float bi0 = bias[qrow], bi1 = bias[qrow + 8];
    #pragma unroll
    for (int nt = 0; nt < 8; nt++) {
        int nc = n0 + nt * 8 + 2 * cl;
        *(float2*)&out[(size_t)qrow * Nn + nc] =
            make_float2(acc[nt][0] + bi0, acc[nt][1] + bi0);
        *(float2*)&out[(size_t)(qrow + 8) * Nn + nc] =
            make_float2(acc[nt][2] + bi1, acc[nt][3] + bi1);
    }
}

// ============================================================================
// kernel 2: fused flash attention on tf32 mma.sync  (unchanged from R2)
// ============================================================================
struct ASmem {
    float Th[Fn][136];   // theta  [k][q],  q-block 128   (reused as O staging)
    float Ph[Fn][72];    // phi    [k][m],  chunk 64
    float Gs[Fn][72];    // g      [k][m],  chunk 64
    float Ps[128][72];   // probs  [q][m]
};

__global__ __launch_bounds__(256, 1) void attn_kernel()
{
    extern __shared__ char smraw[];
    ASmem& sm = *reinterpret_cast<ASmem*>(smraw);

    int b  = blockIdx.y;
    int q0 = blockIdx.x * 128;
    const float* g  = d_proj + ((size_t)0 * Bn + b) * Fn * Nn;
    const float* th = d_proj + ((size_t)1 * Bn + b) * Fn * Nn;
    const float* ph = d_proj + ((size_t)2 * Bn + b) * Fn * Nn;

    int tid  = threadIdx.x;
    int lane = tid & 31, warp = tid >> 5;
    int r = lane >> 2, cl = lane & 3;
    int qrow = warp * 16 + r;

    for (int e = tid; e < Fn * 128 / 4; e += 256) {
        int k = e >> 5, q4 = (e & 31) * 4;
        float4 v = tf4(*(const float4*)&th[(size_t)k * Nn + q0 + q4]);
        *(float4*)&sm.Th[k][q4] = v;
    }

    float oc[16][4];
    #pragma unroll
    for (int i = 0; i < 16; i++)
        #pragma unroll
        for (int j = 0; j < 4; j++) oc[i][j] = 0.f;

    float m0_ = -3.0e38f, m1_ = -3.0e38f;
    float l0_ = 0.f,      l1_ = 0.f;

    __syncthreads();

    for (int mb = 0; mb < Nn; mb += 64) {
        for (int e = tid; e < Fn * 64 / 4; e += 256) {
            int k = e >> 4, n4 = (e & 15) * 4;
            float4 t = tf4(*(const float4*)&ph[(size_t)k * Nn + mb + n4]);
            *(float4*)&sm.Ph[k][n4] = t;
            float4 u = tf4(*(const float4*)&g[(size_t)k * Nn + mb + n4]);
            *(float4*)&sm.Gs[k][n4] = u;
        }
        __syncthreads();

        float sc[8][4];
        #pragma unroll
        for (int i = 0; i < 8; i++)
            #pragma unroll
            for (int j = 0; j < 4; j++) sc[i][j] = 0.f;

        #pragma unroll
        for (int kk = 0; kk < Fn; kk += 8) {
            uint32_t a0 = fbits(sm.Th[kk + cl    ][qrow    ]);
            uint32_t a1 = fbits(sm.Th[kk + cl    ][qrow + 8]);
            uint32_t a2 = fbits(sm.Th[kk + cl + 4][qrow    ]);
            uint32_t a3 = fbits(sm.Th[kk + cl + 4][qrow + 8]);
            #pragma unroll
            for (int nt = 0; nt < 8; nt++) {
                int mc = nt * 8 + r;
                uint32_t b0 = fbits(sm.Ph[kk + cl    ][mc]);
                uint32_t b1 = fbits(sm.Ph[kk + cl + 4][mc]);
                mma8(sc[nt], a0, a1, a2, a3, b0, b1);
            }
        }

        float mx0 = -3.0e38f, mx1 = -3.0e38f;
        #pragma unroll
        for (int nt = 0; nt < 8; nt++) {
            mx0 = fmaxf(mx0, fmaxf(sc[nt][0], sc[nt][1]));
            mx1 = fmaxf(mx1, fmaxf(sc[nt][2], sc[nt][3]));
        }
        #pragma unroll
        for (int o = 1; o < 4; o <<= 1) {
            mx0 = fmaxf(mx0, __shfl_xor_sync(0xffffffffu, mx0, o));
            mx1 = fmaxf(mx1, __shfl_xor_sync(0xffffffffu, mx1, o));
        }
        float nm0 = fmaxf(m0_, mx0), nm1 = fmaxf(m1_, mx1);
        float al0 = __expf(m0_ - nm0), al1 = __expf(m1_ - nm1);
        m0_ = nm0; m1_ = nm1;

        float rs0 = 0.f, rs1 = 0.f;
        #pragma unroll
        for (int nt = 0; nt < 8; nt++) {
            float p0 = __expf(sc[nt][0] - nm0);
            float p1 = __expf(sc[nt][1] - nm0);
            float p2 = __expf(sc[nt][2] - nm1);
            float p3 = __expf(sc[nt][3] - nm1);
            rs0 += p0 + p1; rs1 += p2 + p3;
            int mc = nt * 8 + 2 * cl;
            sm.Ps[qrow    ][mc    ] = __uint_as_float(f2tf(p0));
            sm.Ps[qrow    ][mc + 1] = __uint_as_float(f2tf(p1));
            sm.Ps[qrow + 8][mc    ] = __uint_as_float(f2tf(p2));
            sm.Ps[qrow + 8][mc + 1] = __uint_as_float(f2tf(p3));
        }
        #pragma unroll
        for (int o = 1; o < 4; o <<= 1) {
            rs0 += __shfl_xor_sync(0xffffffffu, rs0, o);
            rs1 += __shfl_xor_sync(0xffffffffu, rs1, o);
        }
        l0_ = l0_ * al0 + rs0;
        l1_ = l1_ * al1 + rs1;

        #pragma unroll
        for (int ft = 0; ft < 16; ft++) {
            oc[ft][0] *= al0; oc[ft][1] *= al0;
            oc[ft][2] *= al1; oc[ft][3] *= al1;
        }

        __syncwarp();

        #pragma unroll
        for (int mk = 0; mk < 64; mk += 8) {
            uint32_t a0 = fbits(sm.Ps[qrow    ][mk + cl    ]);
            uint32_t a1 = fbits(sm.Ps[qrow + 8][mk + cl    ]);
            uint32_t a2 = fbits(sm.Ps[qrow    ][mk + cl + 4]);
            uint32_t a3 = fbits(sm.Ps[qrow + 8][mk + cl + 4]);
            #pragma unroll
            for (int ft = 0; ft < 16; ft++) {
                int fb = ft * 8 + r;
                uint32_t b0 = fbits(sm.Gs[fb][mk + cl    ]);
                uint32_t b1 = fbits(sm.Gs[fb][mk + cl + 4]);
                mma8(oc[ft], a0, a1, a2, a3, b0, b1);
            }
        }
        __syncthreads();
    }

    float li0 = 1.0f / l0_, li1 = 1.0f / l1_;
    float* Os = &sm.Th[0][0];   // pitch 136
    #pragma unroll
    for (int ft = 0; ft < 16; ft++) {
        int fb = ft * 8 + 2 * cl;
        Os[(size_t)(fb    ) * 136 + qrow    ] = oc[ft][0] * li0;
        Os[(size_t)(fb + 1) * 136 + qrow    ] = oc[ft][1] * li0;
        Os[(size_t)(fb    ) * 136 + qrow + 8] = oc[ft][2] * li1;
        Os[(size_t)(fb + 1) * 136 + qrow + 8] = oc[ft][3] * li1;
    }
    __syncthreads();

    float* yb = d_y + (size_t)b * Fn * Nn;
    for (int e = tid; e < Fn * 128 / 4; e += 256) {
        int k = e >> 5, q4 = (e & 31) * 4;
        float4 v = *(const float4*)&Os[(size_t)k * 136 + q4];
        *(float4*)&yb[(size_t)k * Nn + q0 + q4] = v;
    }
}

// ============================================================================
// kernel 3: z = Wz @ y + bz on tf32 mma, with per-tile LN partials
//   M=256 (m-tile 128 via grid.y), K=128, N=4096
// ============================================================================
__global__ __launch_bounds__(256) void zgemm_mma(
    const float* __restrict__ Wz, const float* __restrict__ bz)
{
    extern __shared__ float smem[];
    float* Ws = smem;
    float* Xs = smem + 128 * WS_PITCH;

    int b  = blockIdx.z;
    int m0 = blockIdx.y * 128;
    int n0 = blockIdx.x * 64;
    const float* Y = d_y + (size_t)b * Fn * Nn;
    float* Z = d_z + (size_t)b * CINn * Nn;

    int tid = threadIdx.x;
    int lane = tid & 31, warp = tid >> 5;
    int r = lane >> 2, cl = lane & 3;
    int qrow = warp * 16 + r;

    float acc[8][4];
    #pragma unroll
    for (int i = 0; i < 8; i++)
        #pragma unroll
        for (int j = 0; j < 4; j++) acc[i][j] = 0.f;

    for (int kc = 0; kc < Fn; kc += 64) {
        #pragma unroll
        for (int e = tid; e < 128 * 16; e += 256) {
            int m = e >> 4, k4 = (e & 15) * 4;
            float4 v = tf4(*(const float4*)&Wz[(size_t)(m0 + m) * Fn + kc + k4]);
            *(float4*)&Ws[m * WS_PITCH + k4] = v;
        }
        #pragma unroll
        for (int e = tid; e < 64 * 16; e += 256) {
            int k = e >> 4, n4 = (e & 15) * 4;
            float4 v = tf4(*(const float4*)&Y[(size_t)(kc + k) * Nn + n0 + n4]);
            *(float4*)&Xs[k * XS_PITCH + n4] = v;
        }
        __syncthreads();

        #pragma unroll
        for (int kk = 0; kk < 64; kk += 8) {
            uint32_t a0 = fbits(Ws[qrow       * WS_PITCH + kk + cl    ]);
            uint32_t a1 = fbits(Ws[(qrow + 8) * WS_PITCH + kk + cl    ]);
            uint32_t a2 = fbits(Ws[qrow       * WS_PITCH + kk + cl + 4]);
            uint32_t a3 = fbits(Ws[(qrow + 8) * WS_PITCH + kk + cl + 4]);
            #pragma unroll
            for (int nt = 0; nt < 8; nt++) {
                int mc = nt * 8 + r;
                uint32_t b0 = fbits(Xs[(kk + cl)     * XS_PITCH + mc]);
                uint32_t b1 = fbits(Xs[(kk + cl + 4) * XS_PITCH + mc]);
                mma8(acc[nt], a0, a1, a2, a3, b0, b1);
            }
        }
        __syncthreads();
    }

    float bi0 = bz[m0 + qrow], bi1 = bz[m0 + qrow + 8];
    float lsum = 0.f, lsq = 0.f;
    #pragma unroll
    for (int nt = 0; nt < 8; nt++) {
        int nc = n0 + nt * 8 + 2 * cl;
        float v0 = acc[nt][0] + bi0, v1 = acc[nt][1] + bi0;
        float v2 = acc[nt][2] + bi1, v3 = acc[nt][3] + bi1;
        *(float2*)&Z[(size_t)(m0 + qrow) * Nn + nc]     = make_float2(v0, v1);
        *(float2*)&Z[(size_t)(m0 + qrow + 8) * Nn + nc] = make_float2(v2, v3);
        lsum += v0 + v1 + v2 + v3;
        lsq  += v0 * v0 + v1 * v1 + v2 * v2 + v3 * v3;
    }

    // block reduction of (sum, sumsq) -> d_part
    float* rs = smem;         // reuse (all mma reads complete)
    float* rq = smem + 256;
    rs[tid] = lsum; rq[tid] = lsq;
    __syncthreads();
    #pragma unroll
    for (int s = 128; s > 0; s >>= 1) {
        if (tid < s) { rs[tid] += rs[tid + s]; rq[tid] += rq[tid + s]; }
        __syncthreads();
    }
    if (tid == 0) {
        int idx = b * 128 + blockIdx.y * 64 + blockIdx.x;
        d_part[2 * idx]     = rs[0];
        d_part[2 * idx + 1] = rq[0];
    }
}

// ---------------- kernel 4: per-batch mean / rsig ---------------------------
__global__ __launch_bounds__(128) void stats_kernel()
{
    int b = blockIdx.x;
    int tid = threadIdx.x;
    __shared__ float rs[128], rq[128];
    int idx = b * 128 + tid;
    rs[tid] = d_part[2 * idx];
    rq[tid] = d_part[2 * idx + 1];
    __syncthreads();
    #pragma unroll
    for (int s = 64; s > 0; s >>= 1) {
        if (tid < s) { rs[tid] += rs[tid + s]; rq[tid] += rq[tid + s]; }
        __syncthreads();
    }
    if (tid == 0) {
        float inv = 1.0f / ((float)CINn * (float)Nn);
        float mu  = rs[0] * inv;
        float var = rq[0] * inv - mu * mu;
        d_stats[2 * b]     = mu;
        d_stats[2 * b + 1] = rsqrtf(var + EPSc);
    }
}

// ---------------- kernel 5: LN affine + residual ----------------------------
__global__ __launch_bounds__(256) void finalize_kernel(
    const float* __restrict__ x, const float* __restrict__ lw,
    const float* __restrict__ lb, float* __restrict__ out)
{
    const int per_b4 = CINn * Nn / 4;
    const int tot4   = Bn * per_b4;
    for (int i = blockIdx.x * blockDim.x + threadIdx.x; i < tot4;
         i += gridDim.x * blockDim.x) {
        int b = i / per_b4;
        int r = i - b * per_b4;
        float mu   = d_stats[2 * b];
        float rsig = d_stats[2 * b + 1];
        float4 z  = ((const float4*)d_z)[i];
        float4 xv = ((const float4*)x)[i];
        float4 w  = ((const float4*)lw)[r];
        float4 bb = ((const float4*)lb)[r];
        float4 o;
        o.x = (z.x - mu) * rsig * w.x + bb.x + xv.x;
        o.y = (z.y - mu) * rsig * w.y + bb.y + xv.y;
        o.z = (z.z - mu) * rsig * w.z + bb.z + xv.z;
        o.w = (z.w - mu) * rsig * w.w + bb.w + xv.w;
        ((float4*)out)[i] = o;
    }
}

// ---------------- launch -----------------------------------------------------
extern "C" void kernel_launch(void* const* d_in, const int* in_sizes, int n_in,
                              void* d_out, int out_size)
{
    const float* x   = (const float*)d_in[0];
    const float* Wg  = (const float*)d_in[1];
    const float* bg  = (const float*)d_in[2];
    const float* Wt  = (const float*)d_in[3];
    const float* bt  = (const float*)d_in[4];
    const float* Wp  = (const float*)d_in[5];
    const float* bp  = (const float*)d_in[6];
    const float* Wz  = (const float*)d_in[7];
    const float* bz  = (const float*)d_in[8];
    const float* lnw = (const float*)d_in[9];
    const float* lnb = (const float*)d_in[10];
    float* out = (float*)d_out;

    cudaFuncSetAttribute(attn_kernel, cudaFuncAttributeMaxDynamicSharedMemorySize,
                         (int)sizeof(ASmem));
    cudaFuncSetAttribute(proj_mma, cudaFuncAttributeMaxDynamicSharedMemorySize,
                         GEMM_SMEM);
    cudaFuncSetAttribute(zgemm_mma, cudaFuncAttributeMaxDynamicSharedMemorySize,
                         GEMM_SMEM);

    proj_mma<<<dim3(64, 12), 256, GEMM_SMEM>>>(x, Wg, bg, Wt, bt, Wp, bp);
    attn_kernel<<<dim3(32, 4), 256, sizeof(ASmem)>>>();
    zgemm_mma<<<dim3(64, 2, 4), 256, GEMM_SMEM>>>(Wz, bz);
    stats_kernel<<<4, 128>>>();
    finalize_kernel<<<4096, 256>>>(x, lnw, lnb, out);
}

// round 5
// speedup vs baseline: 3.8004x; 1.0006x over previous
#include <cuda_runtime.h>
#include <math.h>
#include <stdint.h>

#define Bn   4
#define CINn 256
#define Fn   128
#define Nn   4096
#define EPSc 1e-5f

// ---------------- scratch (device globals: no allocation allowed) ----------
__device__ float d_proj[(size_t)3 * Bn * Fn * Nn];   // [proj][b][f][n], 0=g,1=theta,2=phi
__device__ float d_y[(size_t)Bn * Fn * Nn];          // attention output [b][f][n]
__device__ float d_z[(size_t)Bn * CINn * Nn];        // pre-LN output    [b][c][n]
__device__ float d_part[2 * Bn * 128];               // per-tile (sum,sumsq) partials
__device__ float d_stats[2 * Bn];                    // per-batch (mu, rsig)

// ---------------- tf32 helpers ---------------------------------------------
__device__ __forceinline__ uint32_t f2tf(float f) {
    uint32_t r;
    asm("cvt.rna.tf32.f32 %0, %1;" : "=r"(r) : "f"(f));
    return r;
}
__device__ __forceinline__ float4 tf4(float4 v) {
    return make_float4(__uint_as_float(f2tf(v.x)), __uint_as_float(f2tf(v.y)),
                       __uint_as_float(f2tf(v.z)), __uint_as_float(f2tf(v.w)));
}
__device__ __forceinline__ void mma8(float c[4],
        uint32_t a0, uint32_t a1, uint32_t a2, uint32_t a3,
        uint32_t b0, uint32_t b1) {
    asm volatile(
        "mma.sync.aligned.m16n8k8.row.col.f32.tf32.tf32.f32 "
        "{%0,%1,%2,%3}, {%4,%5,%6,%7}, {%8,%9}, {%0,%1,%2,%3};\n"
        : "+f"(c[0]), "+f"(c[1]), "+f"(c[2]), "+f"(c[3])
        : "r"(a0), "r"(a1), "r"(a2), "r"(a3), "r"(b0), "r"(b1));
}
__device__ __forceinline__ uint32_t fbits(float f) { return __float_as_uint(f); }

// ============================================================================
// kernel 1: the three 1x1-conv GEMMs on tf32 mma
//   out[m][n] = sum_k W[m][k] * X[k][n] + bias[m];  M=128, K=256, N=4096
//   8 warps x 16 m-rows, n-tile 64, K chunked by 64.
//   Ws pitch 68 (A frag LDS conflict-free), Xs pitch 72 (B frag conflict-free)
// ============================================================================
#define WS_PITCH 68
#define XS_PITCH 72
#define GEMM_SMEM ((128 * WS_PITCH + 64 * XS_PITCH) * 4)

__global__ __launch_bounds__(256) void proj_mma(
    const float* __restrict__ x,
    const float* __restrict__ Wg, const float* __restrict__ bg,
    const float* __restrict__ Wt, const float* __restrict__ bt,
    const float* __restrict__ Wp, const float* __restrict__ bp)
{
    extern __shared__ float smem[];
    float* Ws = smem;                 // [128][68]
    float* Xs = smem + 128 * WS_PITCH; // [64][72]

    int pb   = blockIdx.y;
    int proj = pb % 3;
    int b    = pb / 3;
    const float* Wm; const float* bias;
    if (proj == 0)      { Wm = Wg; bias = bg; }
    else if (proj == 1) { Wm = Wt; bias = bt; }
    else                { Wm = Wp; bias = bp; }

    const float* X = x + (size_t)b * CINn * Nn;
    float* out = d_proj + ((size_t)proj * Bn + b) * Fn * Nn;
    int n0 = blockIdx.x * 64;

    int tid = threadIdx.x;
    int lane = tid & 31, warp = tid >> 5;
    int r = lane >> 2, cl = lane & 3;
    int qrow = warp * 16 + r;

    float acc[8][4];
    #pragma unroll
    for (int i = 0; i < 8; i++)
        #pragma unroll
        for (int j = 0; j < 4; j++) acc[i][j] = 0.f;

    for (int kc = 0; kc < CINn; kc += 64) {
        // W chunk: [128][64] -> Ws[m][k]
        #pragma unroll
        for (int e = tid; e < 128 * 16; e += 256) {
            int m = e >> 4, k4 = (e & 15) * 4;
            float4 v = tf4(*(const float4*)&Wm[(size_t)m * CINn + kc + k4]);
            *(float4*)&Ws[m * WS_PITCH + k4] = v;
        }
        // X chunk: [64][64] -> Xs[k][n]
        #pragma unroll
        for (int e = tid; e < 64 * 16; e += 256) {
            int k = e >> 4, n4 = (e & 15) * 4;
            float4 v = tf4(*(const float4*)&X[(size_t)(kc + k) * Nn + n0 + n4]);
            *(float4*)&Xs[k * XS_PITCH + n4] = v;
        }
        __syncthreads();

        #pragma unroll
        for (int kk = 0; kk < 64; kk += 8) {
            uint32_t a0 = fbits(Ws[qrow       * WS_PITCH + kk + cl    ]);
            uint32_t a1 = fbits(Ws[(qrow + 8) * WS_PITCH + kk + cl    ]);
            uint32_t a2 = fbits(Ws[qrow       * WS_PITCH + kk + cl + 4]);
            uint32_t a3 = fbits(Ws[(qrow + 8) * WS_PITCH + kk + cl + 4]);
            #pragma unroll
            for (int nt = 0; nt < 8; nt++) {
                int mc = nt * 8 + r;
                uint32_t b0 = fbits(Xs[(kk + cl)     * XS_PITCH + mc]);
                uint32_t b1 = fbits(Xs[(kk + cl + 4) * XS_PITCH + mc]);
                mma8(acc[nt], a0, a1, a2, a3, b0, b1);
            }
        }
        __syncthreads();
    }

    float bi0 = bias[qrow], bi1 = bias[qrow + 8];
    #pragma unroll
    for (int nt = 0; nt < 8; nt++) {
        int nc = n0 + nt * 8 + 2 * cl;
        *(float2*)&out[(size_t)qrow * Nn + nc] =
            make_float2(acc[nt][0] + bi0, acc[nt][1] + bi0);
        *(float2*)&out[(size_t)(qrow + 8) * Nn + nc] =
            make_float2(acc[nt][2] + bi1, acc[nt][3] + bi1);
    }
}

// ============================================================================
// kernel 2: fused flash attention on tf32 mma.sync  (unchanged from R2)
// ============================================================================
struct ASmem {
    float Th[Fn][136];   // theta  [k][q],  q-block 128   (reused as O staging)
    float Ph[Fn][72];    // phi    [k][m],  chunk 64
    float Gs[Fn][72];    // g      [k][m],  chunk 64
    float Ps[128][72];   // probs  [q][m]
};

__global__ __launch_bounds__(256, 1) void attn_kernel()
{
    extern __shared__ char smraw[];
    ASmem& sm = *reinterpret_cast<ASmem*>(smraw);

    int b  = blockIdx.y;
    int q0 = blockIdx.x * 128;
    const float* g  = d_proj + ((size_t)0 * Bn + b) * Fn * Nn;
    const float* th = d_proj + ((size_t)1 * Bn + b) * Fn * Nn;
    const float* ph = d_proj + ((size_t)2 * Bn + b) * Fn * Nn;

    int tid  = threadIdx.x;
    int lane = tid & 31, warp = tid >> 5;
    int r = lane >> 2, cl = lane & 3;
    int qrow = warp * 16 + r;

    for (int e = tid; e < Fn * 128 / 4; e += 256) {
        int k = e >> 5, q4 = (e & 31) * 4;
        float4 v = tf4(*(const float4*)&th[(size_t)k * Nn + q0 + q4]);
        *(float4*)&sm.Th[k][q4] = v;
    }

    float oc[16][4];
    #pragma unroll
    for (int i = 0; i < 16; i++)
        #pragma unroll
        for (int j = 0; j < 4; j++) oc[i][j] = 0.f;

    float m0_ = -3.0e38f, m1_ = -3.0e38f;
    float l0_ = 0.f,      l1_ = 0.f;

    __syncthreads();

    for (int mb = 0; mb < Nn; mb += 64) {
        for (int e = tid; e < Fn * 64 / 4; e += 256) {
            int k = e >> 4, n4 = (e & 15) * 4;
            float4 t = tf4(*(const float4*)&ph[(size_t)k * Nn + mb + n4]);
            *(float4*)&sm.Ph[k][n4] = t;
            float4 u = tf4(*(const float4*)&g[(size_t)k * Nn + mb + n4]);
            *(float4*)&sm.Gs[k][n4] = u;
        }
        __syncthreads();

        float sc[8][4];
        #pragma unroll
        for (int i = 0; i < 8; i++)
            #pragma unroll
            for (int j = 0; j < 4; j++) sc[i][j] = 0.f;

        #pragma unroll
        for (int kk = 0; kk < Fn; kk += 8) {
            uint32_t a0 = fbits(sm.Th[kk + cl    ][qrow    ]);
            uint32_t a1 = fbits(sm.Th[kk + cl    ][qrow + 8]);
            uint32_t a2 = fbits(sm.Th[kk + cl + 4][qrow    ]);
            uint32_t a3 = fbits(sm.Th[kk + cl + 4][qrow + 8]);
            #pragma unroll
            for (int nt = 0; nt < 8; nt++) {
                int mc = nt * 8 + r;
                uint32_t b0 = fbits(sm.Ph[kk + cl    ][mc]);
                uint32_t b1 = fbits(sm.Ph[kk + cl + 4][mc]);
                mma8(sc[nt], a0, a1, a2, a3, b0, b1);
            }
        }

        float mx0 = -3.0e38f, mx1 = -3.0e38f;
        #pragma unroll
        for (int nt = 0; nt < 8; nt++) {
            mx0 = fmaxf(mx0, fmaxf(sc[nt][0], sc[nt][1]));
            mx1 = fmaxf(mx1, fmaxf(sc[nt][2], sc[nt][3]));
        }
        #pragma unroll
        for (int o = 1; o < 4; o <<= 1) {
            mx0 = fmaxf(mx0, __shfl_xor_sync(0xffffffffu, mx0, o));
            mx1 = fmaxf(mx1, __shfl_xor_sync(0xffffffffu, mx1, o));
        }
        float nm0 = fmaxf(m0_, mx0), nm1 = fmaxf(m1_, mx1);
        float al0 = __expf(m0_ - nm0), al1 = __expf(m1_ - nm1);
        m0_ = nm0; m1_ = nm1;

        float rs0 = 0.f, rs1 = 0.f;
        #pragma unroll
        for (int nt = 0; nt < 8; nt++) {
            float p0 = __expf(sc[nt][0] - nm0);
            float p1 = __expf(sc[nt][1] - nm0);
            float p2 = __expf(sc[nt][2] - nm1);
            float p3 = __expf(sc[nt][3] - nm1);
            rs0 += p0 + p1; rs1 += p2 + p3;
            int mc = nt * 8 + 2 * cl;
            sm.Ps[qrow    ][mc    ] = __uint_as_float(f2tf(p0));
            sm.Ps[qrow    ][mc + 1] = __uint_as_float(f2tf(p1));
            sm.Ps[qrow + 8][mc    ] = __uint_as_float(f2tf(p2));
            sm.Ps[qrow + 8][mc + 1] = __uint_as_float(f2tf(p3));
        }
        #pragma unroll
        for (int o = 1; o < 4; o <<= 1) {
            rs0 += __shfl_xor_sync(0xffffffffu, rs0, o);
            rs1 += __shfl_xor_sync(0xffffffffu, rs1, o);
        }
        l0_ = l0_ * al0 + rs0;
        l1_ = l1_ * al1 + rs1;

        #pragma unroll
        for (int ft = 0; ft < 16; ft++) {
            oc[ft][0] *= al0; oc[ft][1] *= al0;
            oc[ft][2] *= al1; oc[ft][3] *= al1;
        }

        __syncwarp();

        #pragma unroll
        for (int mk = 0; mk < 64; mk += 8) {
            uint32_t a0 = fbits(sm.Ps[qrow    ][mk + cl    ]);
            uint32_t a1 = fbits(sm.Ps[qrow + 8][mk + cl    ]);
            uint32_t a2 = fbits(sm.Ps[qrow    ][mk + cl + 4]);
            uint32_t a3 = fbits(sm.Ps[qrow + 8][mk + cl + 4]);
            #pragma unroll
            for (int ft = 0; ft < 16; ft++) {
                int fb = ft * 8 + r;
                uint32_t b0 = fbits(sm.Gs[fb][mk + cl    ]);
                uint32_t b1 = fbits(sm.Gs[fb][mk + cl + 4]);
                mma8(oc[ft], a0, a1, a2, a3, b0, b1);
            }
        }
        __syncthreads();
    }

    float li0 = 1.0f / l0_, li1 = 1.0f / l1_;
    float* Os = &sm.Th[0][0];   // pitch 136
    #pragma unroll
    for (int ft = 0; ft < 16; ft++) {
        int fb = ft * 8 + 2 * cl;
        Os[(size_t)(fb    ) * 136 + qrow    ] = oc[ft][0] * li0;
        Os[(size_t)(fb + 1) * 136 + qrow    ] = oc[ft][1] * li0;
        Os[(size_t)(fb    ) * 136 + qrow + 8] = oc[ft][2] * li1;
        Os[(size_t)(fb + 1) * 136 + qrow + 8] = oc[ft][3] * li1;
    }
    __syncthreads();

    float* yb = d_y + (size_t)b * Fn * Nn;
    for (int e = tid; e < Fn * 128 / 4; e += 256) {
        int k = e >> 5, q4 = (e & 31) * 4;
        float4 v = *(const float4*)&Os[(size_t)k * 136 + q4];
        *(float4*)&yb[(size_t)k * Nn + q0 + q4] = v;
    }
}

// ============================================================================
// kernel 3: z = Wz @ y + bz on tf32 mma, with per-tile LN partials
//   M=256 (m-tile 128 via grid.y), K=128, N=4096
// ============================================================================
__global__ __launch_bounds__(256) void zgemm_mma(
    const float* __restrict__ Wz, const float* __restrict__ bz)
{
    extern __shared__ float smem[];
    float* Ws = smem;
    float* Xs = smem + 128 * WS_PITCH;

    int b  = blockIdx.z;
    int m0 = blockIdx.y * 128;
    int n0 = blockIdx.x * 64;
    const float* Y = d_y + (size_t)b * Fn * Nn;
    float* Z = d_z + (size_t)b * CINn * Nn;

    int tid = threadIdx.x;
    int lane = tid & 31, warp = tid >> 5;
    int r = lane >> 2, cl = lane & 3;
    int qrow = warp * 16 + r;

    float acc[8][4];
    #pragma unroll
    for (int i = 0; i < 8; i++)
        #pragma unroll
        for (int j = 0; j < 4; j++) acc[i][j] = 0.f;

    for (int kc = 0; kc < Fn; kc += 64) {
        #pragma unroll
        for (int e = tid; e < 128 * 16; e += 256) {
            int m = e >> 4, k4 = (e & 15) * 4;
            float4 v = tf4(*(const float4*)&Wz[(size_t)(m0 + m) * Fn + kc + k4]);
            *(float4*)&Ws[m * WS_PITCH + k4] = v;
        }
        #pragma unroll
        for (int e = tid; e < 64 * 16; e += 256) {
            int k = e >> 4, n4 = (e & 15) * 4;
            float4 v = tf4(*(const float4*)&Y[(size_t)(kc + k) * Nn + n0 + n4]);
            *(float4*)&Xs[k * XS_PITCH + n4] = v;
        }
        __syncthreads();

        #pragma unroll
        for (int kk = 0; kk < 64; kk += 8) {
            uint32_t a0 = fbits(Ws[qrow       * WS_PITCH + kk + cl    ]);
            uint32_t a1 = fbits(Ws[(qrow + 8) * WS_PITCH + kk + cl    ]);
            uint32_t a2 = fbits(Ws[qrow       * WS_PITCH + kk + cl + 4]);
            uint32_t a3 = fbits(Ws[(qrow + 8) * WS_PITCH + kk + cl + 4]);
            #pragma unroll
            for (int nt = 0; nt < 8; nt++) {
                int mc = nt * 8 + r;
                uint32_t b0 = fbits(Xs[(kk + cl)     * XS_PITCH + mc]);
                uint32_t b1 = fbits(Xs[(kk + cl + 4) * XS_PITCH + mc]);
                mma8(acc[nt], a0, a1, a2, a3, b0, b1);
            }
        }
        __syncthreads();
    }

    float bi0 = bz[m0 + qrow], bi1 = bz[m0 + qrow + 8];
    float lsum = 0.f, lsq = 0.f;
    #pragma unroll
    for (int nt = 0; nt < 8; nt++) {
        int nc = n0 + nt * 8 + 2 * cl;
        float v0 = acc[nt][0] + bi0, v1 = acc[nt][1] + bi0;
        float v2 = acc[nt][2] + bi1, v3 = acc[nt][3] + bi1;
        *(float2*)&Z[(size_t)(m0 + qrow) * Nn + nc]     = make_float2(v0, v1);
        *(float2*)&Z[(size_t)(m0 + qrow + 8) * Nn + nc] = make_float2(v2, v3);
        lsum += v0 + v1 + v2 + v3;
        lsq  += v0 * v0 + v1 * v1 + v2 * v2 + v3 * v3;
    }

    // block reduction of (sum, sumsq) -> d_part
    float* rs = smem;         // reuse (all mma reads complete)
    float* rq = smem + 256;
    rs[tid] = lsum; rq[tid] = lsq;
    __syncthreads();
    #pragma unroll
    for (int s = 128; s > 0; s >>= 1) {
        if (tid < s) { rs[tid] += rs[tid + s]; rq[tid] += rq[tid + s]; }
        __syncthreads();
    }
    if (tid == 0) {
        int idx = b * 128 + blockIdx.y * 64 + blockIdx.x;
        d_part[2 * idx]     = rs[0];
        d_part[2 * idx + 1] = rq[0];
    }
}

// ---------------- kernel 4: per-batch mean / rsig ---------------------------
__global__ __launch_bounds__(128) void stats_kernel()
{
    int b = blockIdx.x;
    int tid = threadIdx.x;
    __shared__ float rs[128], rq[128];
    int idx = b * 128 + tid;
    rs[tid] = d_part[2 * idx];
    rq[tid] = d_part[2 * idx + 1];
    __syncthreads();
    #pragma unroll
    for (int s = 64; s > 0; s >>= 1) {
        if (tid < s) { rs[tid] += rs[tid + s]; rq[tid] += rq[tid + s]; }
        __syncthreads();
    }
    if (tid == 0) {
        float inv = 1.0f / ((float)CINn * (float)Nn);
        float mu  = rs[0] * inv;
        float var = rq[0] * inv - mu * mu;
        d_stats[2 * b]     = mu;
        d_stats[2 * b + 1] = rsqrtf(var + EPSc);
    }
}

// ---------------- kernel 5: LN affine + residual ----------------------------
__global__ __launch_bounds__(256) void finalize_kernel(
    const float* __restrict__ x, const float* __restrict__ lw,
    const float* __restrict__ lb, float* __restrict__ out)
{
    const int per_b4 = CINn * Nn / 4;
    const int tot4   = Bn * per_b4;
    for (int i = blockIdx.x * blockDim.x + threadIdx.x; i < tot4;
         i += gridDim.x * blockDim.x) {
        int b = i / per_b4;
        int r = i - b * per_b4;
        float mu   = d_stats[2 * b];
        float rsig = d_stats[2 * b + 1];
        float4 z  = ((const float4*)d_z)[i];
        float4 xv = ((const float4*)x)[i];
        float4 w  = ((const float4*)lw)[r];
        float4 bb = ((const float4*)lb)[r];
        float4 o;
        o.x = (z.x - mu) * rsig * w.x + bb.x + xv.x;
        o.y = (z.y - mu) * rsig * w.y + bb.y + xv.y;
        o.z = (z.z - mu) * rsig * w.z + bb.z + xv.z;
        o.w = (z.w - mu) * rsig * w.w + bb.w + xv.w;
        ((float4*)out)[i] = o;
    }
}

// ---------------- launch -----------------------------------------------------
extern "C" void kernel_launch(void* const* d_in, const int* in_sizes, int n_in,
                              void* d_out, int out_size)
{
    const float* x   = (const float*)d_in[0];
    const float* Wg  = (const float*)d_in[1];
    const float* bg  = (const float*)d_in[2];
    const float* Wt  = (const float*)d_in[3];
    const float* bt  = (const float*)d_in[4];
    const float* Wp  = (const float*)d_in[5];
    const float* bp  = (const float*)d_in[6];
    const float* Wz  = (const float*)d_in[7];
    const float* bz  = (const float*)d_in[8];
    const float* lnw = (const float*)d_in[9];
    const float* lnb = (const float*)d_in[10];
    float* out = (float*)d_out;

    cudaFuncSetAttribute(attn_kernel, cudaFuncAttributeMaxDynamicSharedMemorySize,
                         (int)sizeof(ASmem));
    cudaFuncSetAttribute(proj_mma, cudaFuncAttributeMaxDynamicSharedMemorySize,
                         GEMM_SMEM);
    cudaFuncSetAttribute(zgemm_mma, cudaFuncAttributeMaxDynamicSharedMemorySize,
                         GEMM_SMEM);

    proj_mma<<<dim3(64, 12), 256, GEMM_SMEM>>>(x, Wg, bg, Wt, bt, Wp, bp);
    attn_kernel<<<dim3(32, 4), 256, sizeof(ASmem)>>>();
    zgemm_mma<<<dim3(64, 2, 4), 256, GEMM_SMEM>>>(Wz, bz);
    stats_kernel<<<4, 128>>>();
    finalize_kernel<<<4096, 256>>>(x, lnw, lnb, out);
}

// round 7
// speedup vs baseline: 7.2505x; 1.9078x over previous
#include <cuda_runtime.h>
#include <cuda_fp16.h>
#include <math.h>
#include <stdint.h>

#define Bn   4
#define CINn 256
#define Fn   128
#define Nn   4096
#define EPSc 1e-5f

// ---------------- scratch (device globals: no allocation allowed) ----------
__device__ __half d_t16[(size_t)Bn * Nn * Fn];   // theta, [b][n][f]  (transposed)
__device__ __half d_p16[(size_t)Bn * Nn * Fn];   // phi,   [b][n][f]  (transposed)
__device__ __half d_g16[(size_t)Bn * Fn * Nn];   // g,     [b][f][n]  (natural)
__device__ __half d_y16[(size_t)Bn * Nn * Fn];   // y,     [b][n][f]
__device__ float  d_z[(size_t)Bn * CINn * Nn];   // pre-LN output [b][c][n]
__device__ float  d_part[2 * Bn * 128];          // per-tile (sum,sumsq) partials
__device__ float  d_stats[2 * Bn];               // per-batch (mu, rsig)

// ---------------- mma helpers ----------------------------------------------
__device__ __forceinline__ uint32_t f2tf(float f) {
    uint32_t r;
    asm("cvt.rna.tf32.f32 %0, %1;" : "=r"(r) : "f"(f));
    return r;
}
__device__ __forceinline__ float4 tf4(float4 v) {
    return make_float4(__uint_as_float(f2tf(v.x)), __uint_as_float(f2tf(v.y)),
                       __uint_as_float(f2tf(v.z)), __uint_as_float(f2tf(v.w)));
}
__device__ __forceinline__ void mma8(float c[4],
        uint32_t a0, uint32_t a1, uint32_t a2, uint32_t a3,
        uint32_t b0, uint32_t b1) {
    asm volatile(
        "mma.sync.aligned.m16n8k8.row.col.f32.tf32.tf32.f32 "
        "{%0,%1,%2,%3}, {%4,%5,%6,%7}, {%8,%9}, {%0,%1,%2,%3};\n"
        : "+f"(c[0]), "+f"(c[1]), "+f"(c[2]), "+f"(c[3])
        : "r"(a0), "r"(a1), "r"(a2), "r"(a3), "r"(b0), "r"(b1));
}
__device__ __forceinline__ void mma16(float c[4],
        uint32_t a0, uint32_t a1, uint32_t a2, uint32_t a3,
        uint32_t b0, uint32_t b1) {
    asm volatile(
        "mma.sync.aligned.m16n8k16.row.col.f32.f16.f16.f32 "
        "{%0,%1,%2,%3}, {%4,%5,%6,%7}, {%8,%9}, {%0,%1,%2,%3};\n"
        : "+f"(c[0]), "+f"(c[1]), "+f"(c[2]), "+f"(c[3])
        : "r"(a0), "r"(a1), "r"(a2), "r"(a3), "r"(b0), "r"(b1));
}
__device__ __forceinline__ uint32_t fbits(float f) { return __float_as_uint(f); }
__device__ __forceinline__ uint32_t ldu32(const __half* p) {
    return *(const uint32_t*)p;
}

// ============================================================================
// kernel 1: the three 1x1-conv GEMMs on tf32 mma (fp32 x input), fp16 output
//   layouts tailored for the attention kernel's fp16 fragments.
// ============================================================================
#define WS_PITCH 68
#define XS_PITCH 72
#define GEMM_SMEM ((128 * WS_PITCH + 64 * XS_PITCH) * 4)

__global__ __launch_bounds__(256) void proj_mma(
    const float* __restrict__ x,
    const float* __restrict__ Wg, const float* __restrict__ bg,
    const float* __restrict__ Wt, const float* __restrict__ bt,
    const float* __restrict__ Wp, const float* __restrict__ bp)
{
    extern __shared__ float smem[];
    float* Ws = smem;                  // [128][68]
    float* Xs = smem + 128 * WS_PITCH; // [64][72]

    int pb   = blockIdx.y;
    int proj = pb % 3;
    int b    = pb / 3;
    const float* Wm; const float* bias;
    if (proj == 0)      { Wm = Wg; bias = bg; }
    else if (proj == 1) { Wm = Wt; bias = bt; }
    else                { Wm = Wp; bias = bp; }

    const float* X = x + (size_t)b * CINn * Nn;
    int n0 = blockIdx.x * 64;

    int tid = threadIdx.x;
    int lane = tid & 31, warp = tid >> 5;
    int r = lane >> 2, cl = lane & 3;
    int qrow = warp * 16 + r;

    float acc[8][4];
    #pragma unroll
    for (int i = 0; i < 8; i++)
        #pragma unroll
        for (int j = 0; j < 4; j++) acc[i][j] = 0.f;

    for (int kc = 0; kc < CINn; kc += 64) {
        #pragma unroll
        for (int e = tid; e < 128 * 16; e += 256) {
            int m = e >> 4, k4 = (e & 15) * 4;
            float4 v = tf4(*(const float4*)&Wm[(size_t)m * CINn + kc + k4]);
            *(float4*)&Ws[m * WS_PITCH + k4] = v;
        }
        #pragma unroll
        for (int e = tid; e < 64 * 16; e += 256) {
            int k = e >> 4, n4 = (e & 15) * 4;
            float4 v = tf4(*(const float4*)&X[(size_t)(kc + k) * Nn + n0 + n4]);
            *(float4*)&Xs[k * XS_PITCH + n4] = v;
        }
        __syncthreads();

        #pragma unroll
        for (int kk = 0; kk < 64; kk += 8) {
            uint32_t a0 = fbits(Ws[qrow       * WS_PITCH + kk + cl    ]);
            uint32_t a1 = fbits(Ws[(qrow + 8) * WS_PITCH + kk + cl    ]);
            uint32_t a2 = fbits(Ws[qrow       * WS_PITCH + kk + cl + 4]);
            uint32_t a3 = fbits(Ws[(qrow + 8) * WS_PITCH + kk + cl + 4]);
            #pragma unroll
            for (int nt = 0; nt < 8; nt++) {
                int mc = nt * 8 + r;
                uint32_t b0 = fbits(Xs[(kk + cl)     * XS_PITCH + mc]);
                uint32_t b1 = fbits(Xs[(kk + cl + 4) * XS_PITCH + mc]);
                mma8(acc[nt], a0, a1, a2, a3, b0, b1);
            }
        }
        __syncthreads();
    }

    float bi0 = bias[qrow], bi1 = bias[qrow + 8];
    if (proj == 0) {
        // g : [f][n] fp16, half2 along n
        __half* out = d_g16 + (size_t)b * Fn * Nn;
        #pragma unroll
        for (int nt = 0; nt < 8; nt++) {
            int nc = n0 + nt * 8 + 2 * cl;
            *(__half2*)&out[(size_t)qrow * Nn + nc] =
                __floats2half2_rn(acc[nt][0] + bi0, acc[nt][1] + bi0);
            *(__half2*)&out[(size_t)(qrow + 8) * Nn + nc] =
                __floats2half2_rn(acc[nt][2] + bi1, acc[nt][3] + bi1);
        }
    } else {
        // theta / phi : transposed [n][f] fp16
        __half* out = (proj == 1 ? d_t16 : d_p16) + (size_t)b * Nn * Fn;
        #pragma unroll
        for (int nt = 0; nt < 8; nt++) {
            int nc = n0 + nt * 8 + 2 * cl;
            out[(size_t)nc       * Fn + qrow    ] = __float2half_rn(acc[nt][0] + bi0);
            out[(size_t)(nc + 1) * Fn + qrow    ] = __float2half_rn(acc[nt][1] + bi0);
            out[(size_t)nc       * Fn + qrow + 8] = __float2half_rn(acc[nt][2] + bi1);
            out[(size_t)(nc + 1) * Fn + qrow + 8] = __float2half_rn(acc[nt][3] + bi1);
        }
    }
}

// ============================================================================
// kernel 2: fused flash attention on fp16 mma (m16n8k16), fp32 accumulate
// ============================================================================
struct ASmem {
    __half Th[128][136];  // theta [q][f]
    __half Ph[64][136];   // phi   [m][f]
    __half Gs[Fn][72];    // g     [f][m]
    __half Ps[128][72];   // probs [q][m]
};

__global__ __launch_bounds__(256, 1) void attn_kernel()
{
    extern __shared__ char smraw[];
    ASmem& sm = *reinterpret_cast<ASmem*>(smraw);

    int b  = blockIdx.y;
    int q0 = blockIdx.x * 128;
    const __half* t16 = d_t16 + (size_t)b * Nn * Fn;
    const __half* p16 = d_p16 + (size_t)b * Nn * Fn;
    const __half* g16 = d_g16 + (size_t)b * Fn * Nn;

    int tid  = threadIdx.x;
    int lane = tid & 31, warp = tid >> 5;
    int r = lane >> 2, cl = lane & 3;
    int qrow = warp * 16 + r;

    // theta block: pure fp16 copy, [q][f]
    #pragma unroll
    for (int e = tid; e < 128 * 16; e += 256) {
        int q = e >> 4, c8 = (e & 15) * 8;
        *(uint4*)&sm.Th[q][c8] = *(const uint4*)&t16[(size_t)(q0 + q) * Fn + c8];
    }

    float oc[16][4];
    #pragma unroll
    for (int i = 0; i < 16; i++)
        #pragma unroll
        for (int j = 0; j < 4; j++) oc[i][j] = 0.f;

    float m0_ = -3.0e38f, m1_ = -3.0e38f;
    float l0_ = 0.f,      l1_ = 0.f;

    __syncthreads();

    for (int mb = 0; mb < Nn; mb += 64) {
        // chunk fills: pure fp16 copies
        #pragma unroll
        for (int e = tid; e < 64 * 16; e += 256) {
            int m = e >> 4, c8 = (e & 15) * 8;
            *(uint4*)&sm.Ph[m][c8] = *(const uint4*)&p16[(size_t)(mb + m) * Fn + c8];
        }
        #pragma unroll
        for (int e = tid; e < 128 * 8; e += 256) {
            int f = e >> 3, c8 = (e & 7) * 8;
            *(uint4*)&sm.Gs[f][c8] = *(const uint4*)&g16[(size_t)f * Nn + mb + c8];
        }
        __syncthreads();

        // ---- S = theta phi^T : warp computes 16q x 64m ----
        float sc[8][4];
        #pragma unroll
        for (int i = 0; i < 8; i++)
            #pragma unroll
            for (int j = 0; j < 4; j++) sc[i][j] = 0.f;

        #pragma unroll
        for (int kk = 0; kk < Fn; kk += 16) {
            uint32_t a0 = ldu32(&sm.Th[qrow    ][kk + 2 * cl    ]);
            uint32_t a1 = ldu32(&sm.Th[qrow + 8][kk + 2 * cl    ]);
            uint32_t a2 = ldu32(&sm.Th[qrow    ][kk + 2 * cl + 8]);
            uint32_t a3 = ldu32(&sm.Th[qrow + 8][kk + 2 * cl + 8]);
            #pragma unroll
            for (int nt = 0; nt < 8; nt++) {
                int mc = nt * 8 + r;
                uint32_t b0 = ldu32(&sm.Ph[mc][kk + 2 * cl    ]);
                uint32_t b1 = ldu32(&sm.Ph[mc][kk + 2 * cl + 8]);
                mma16(sc[nt], a0, a1, a2, a3, b0, b1);
            }
        }

        // ---- online softmax (warp-local) ----
        float mx0 = -3.0e38f, mx1 = -3.0e38f;
        #pragma unroll
        for (int nt = 0; nt < 8; nt++) {
            mx0 = fmaxf(mx0, fmaxf(sc[nt][0], sc[nt][1]));
            mx1 = fmaxf(mx1, fmaxf(sc[nt][2], sc[nt][3]));
        }
        #pragma unroll
        for (int o = 1; o < 4; o <<= 1) {
            mx0 = fmaxf(mx0, __shfl_xor_sync(0xffffffffu, mx0, o));
            mx1 = fmaxf(mx1, __shfl_xor_sync(0xffffffffu, mx1, o));
        }
        float nm0 = fmaxf(m0_, mx0), nm1 = fmaxf(m1_, mx1);
        float al0 = __expf(m0_ - nm0), al1 = __expf(m1_ - nm1);
        m0_ = nm0; m1_ = nm1;

        float rs0 = 0.f, rs1 = 0.f;
        #pragma unroll
        for (int nt = 0; nt < 8; nt++) {
            float p0 = __expf(sc[nt][0] - nm0);
            float p1 = __expf(sc[nt][1] - nm0);
            float p2 = __expf(sc[nt][2] - nm1);
            float p3 = __expf(sc[nt][3] - nm1);
            rs0 += p0 + p1; rs1 += p2 + p3;
            int mc = nt * 8 + 2 * cl;
            *(__half2*)&sm.Ps[qrow    ][mc] = __floats2half2_rn(p0, p1);
            *(__half2*)&sm.Ps[qrow + 8][mc] = __floats2half2_rn(p2, p3);
        }
        #pragma unroll
        for (int o = 1; o < 4; o <<= 1) {
            rs0 += __shfl_xor_sync(0xffffffffu, rs0, o);
            rs1 += __shfl_xor_sync(0xffffffffu, rs1, o);
        }
        l0_ = l0_ * al0 + rs0;
        l1_ = l1_ * al1 + rs1;

        #pragma unroll
        for (int ft = 0; ft < 16; ft++) {
            oc[ft][0] *= al0; oc[ft][1] *= al0;
            oc[ft][2] *= al1; oc[ft][3] *= al1;
        }

        __syncwarp();

        // ---- O += P G^T : warp computes 16q x 128f ----
        #pragma unroll
        for (int mk = 0; mk < 64; mk += 16) {
            uint32_t a0 = ldu32(&sm.Ps[qrow    ][mk + 2 * cl    ]);
            uint32_t a1 = ldu32(&sm.Ps[qrow + 8][mk + 2 * cl    ]);
            uint32_t a2 = ldu32(&sm.Ps[qrow    ][mk + 2 * cl + 8]);
            uint32_t a3 = ldu32(&sm.Ps[qrow + 8][mk + 2 * cl + 8]);
            #pragma unroll
            for (int ft = 0; ft < 16; ft++) {
                int fb = ft * 8 + r;
                uint32_t b0 = ldu32(&sm.Gs[fb][mk + 2 * cl    ]);
                uint32_t b1 = ldu32(&sm.Gs[fb][mk + 2 * cl + 8]);
                mma16(oc[ft], a0, a1, a2, a3, b0, b1);
            }
        }
        __syncthreads();
    }

    // ---- epilogue: normalize, write y [n][f] fp16 straight from registers ----
    float li0 = 1.0f / l0_, li1 = 1.0f / l1_;
    __half* yb = d_y16 + ((size_t)b * Nn + q0) * Fn;
    #pragma unroll
    for (int ft = 0; ft < 16; ft++) {
        int fb = ft * 8 + 2 * cl;
        *(__half2*)&yb[(size_t)qrow * Fn + fb] =
            __floats2half2_rn(oc[ft][0] * li0, oc[ft][1] * li0);
        *(__half2*)&yb[(size_t)(qrow + 8) * Fn + fb] =
            __floats2half2_rn(oc[ft][2] * li1, oc[ft][3] * li1);
    }
}

// ============================================================================
// kernel 3: z = Wz @ y + bz on fp16 mma (single K pass), LN partials fused
//   ZW_PITCH = 136 halves (128 k + 8 pad): row stride 68 words = 4 mod 32
//   -> fragment LDS (4r + cl) hits all 32 banks, conflict-free.
// ============================================================================
#define ZW_PITCH 136
#define ZY_PITCH 136
#define ZG_SMEM (128 * ZW_PITCH * 2 + 64 * ZY_PITCH * 2)

__global__ __launch_bounds__(256) void zgemm_mma(
    const float* __restrict__ Wz, const float* __restrict__ bz)
{
    extern __shared__ char zsm[];
    __half* Ws = (__half*)zsm;                        // [128][136]
    __half* Ys = (__half*)(zsm + 128 * ZW_PITCH * 2); // [64][136]

    int b  = blockIdx.z;
    int m0 = blockIdx.y * 128;
    int n0 = blockIdx.x * 64;
    const __half* Y16 = d_y16 + (size_t)b * Nn * Fn;
    float* Z = d_z + (size_t)b * CINn * Nn;

    int tid = threadIdx.x;
    int lane = tid & 31, warp = tid >> 5;
    int r = lane >> 2, cl = lane & 3;
    int qrow = warp * 16 + r;

    // fill A (Wz fp32 -> fp16)
    #pragma unroll
    for (int e = tid; e < 128 * 32; e += 256) {
        int m = e >> 5, k4 = (e & 31) * 4;
        float4 v = *(const float4*)&Wz[(size_t)(m0 + m) * Fn + k4];
        *(__half2*)&Ws[m * ZW_PITCH + k4]     = __floats2half2_rn(v.x, v.y);
        *(__half2*)&Ws[m * ZW_PITCH + k4 + 2] = __floats2half2_rn(v.z, v.w);
    }
    // fill B (y16 copy)
    #pragma unroll
    for (int e = tid; e < 64 * 16; e += 256) {
        int n = e >> 4, c8 = (e & 15) * 8;
        *(uint4*)&Ys[n * ZY_PITCH + c8] = *(const uint4*)&Y16[(size_t)(n0 + n) * Fn + c8];
    }
    __syncthreads();

    float acc[8][4];
    #pragma unroll
    for (int i = 0; i < 8; i++)
        #pragma unroll
        for (int j = 0; j < 4; j++) acc[i][j] = 0.f;

    #pragma unroll
    for (int kk = 0; kk < Fn; kk += 16) {
        uint32_t a0 = ldu32(&Ws[qrow       * ZW_PITCH + kk + 2 * cl    ]);
        uint32_t a1 = ldu32(&Ws[(qrow + 8) * ZW_PITCH + kk + 2 * cl    ]);
        uint32_t a2 = ldu32(&Ws[qrow       * ZW_PITCH + kk + 2 * cl + 8]);
        uint32_t a3 = ldu32(&Ws[(qrow + 8) * ZW_PITCH + kk + 2 * cl + 8]);
        #pragma unroll
        for (int nt = 0; nt < 8; nt++) {
            int nc = nt * 8 + r;
            uint32_t b0 = ldu32(&Ys[nc * ZY_PITCH + kk + 2 * cl    ]);
            uint32_t b1 = ldu32(&Ys[nc * ZY_PITCH + kk + 2 * cl + 8]);
            mma16(acc[nt], a0, a1, a2, a3, b0, b1);
        }
    }
    __syncthreads();

    float bi0 = bz[m0 + qrow], bi1 = bz[m0 + qrow + 8];
    float lsum = 0.f, lsq = 0.f;
    #pragma unroll
    for (int nt = 0; nt < 8; nt++) {
        int nc = n0 + nt * 8 + 2 * cl;
        float v0 = acc[nt][0] + bi0, v1 = acc[nt][1] + bi0;
        float v2 = acc[nt][2] + bi1, v3 = acc[nt][3] + bi1;
        *(float2*)&Z[(size_t)(m0 + qrow) * Nn + nc]     = make_float2(v0, v1);
        *(float2*)&Z[(size_t)(m0 + qrow + 8) * Nn + nc] = make_float2(v2, v3);
        lsum += v0 + v1 + v2 + v3;
        lsq  += v0 * v0 + v1 * v1 + v2 * v2 + v3 * v3;
    }

    float* rs = (float*)zsm;          // safe: all smem reads done
    float* rq = rs + 256;
    rs[tid] = lsum; rq[tid] = lsq;
    __syncthreads();
    #pragma unroll
    for (int s = 128; s > 0; s >>= 1) {
        if (tid < s) { rs[tid] += rs[tid + s]; rq[tid] += rq[tid + s]; }
        __syncthreads();
    }
    if (tid == 0) {
        int idx = b * 128 + blockIdx.y * 64 + blockIdx.x;
        d_part[2 * idx]     = rs[0];
        d_part[2 * idx + 1] = rq[0];
    }
}

// ---------------- kernel 4: per-batch mean / rsig ---------------------------
__global__ __launch_bounds__(128) void stats_kernel()
{
    int b = blockIdx.x;
    int tid = threadIdx.x;
    __shared__ float rs[128], rq[128];
    int idx = b * 128 + tid;
    rs[tid] = d_part[2 * idx];
    rq[tid] = d_part[2 * idx + 1];
    __syncthreads();
    #pragma unroll
    for (int s = 64; s > 0; s >>= 1) {
        if (tid < s) { rs[tid] += rs[tid + s]; rq[tid] += rq[tid + s]; }
        __syncthreads();
    }
    if (tid == 0) {
        float inv = 1.0f / ((float)CINn * (float)Nn);
        float mu  = rs[0] * inv;
        float var = rq[0] * inv - mu * mu;
        d_stats[2 * b]     = mu;
        d_stats[2 * b + 1] = rsqrtf(var + EPSc);
    }
}

// ---------------- kernel 5: LN affine + residual ----------------------------
__global__ __launch_bounds__(256) void finalize_kernel(
    const float* __restrict__ x, const float* __restrict__ lw,
    const float* __restrict__ lb, float* __restrict__ out)
{
    const int per_b4 = CINn * Nn / 4;
    const int tot4   = Bn * per_b4;
    for (int i = blockIdx.x * blockDim.x + threadIdx.x; i < tot4;
         i += gridDim.x * blockDim.x) {
        int b = i / per_b4;
        int r = i - b * per_b4;
        float mu   = d_stats[2 * b];
        float rsig = d_stats[2 * b + 1];
        float4 z  = ((const float4*)d_z)[i];
        float4 xv = ((const float4*)x)[i];
        float4 w  = ((const float4*)lw)[r];
        float4 bb = ((const float4*)lb)[r];
        float4 o;
        o.x = (z.x - mu) * rsig * w.x + bb.x + xv.x;
        o.y = (z.y - mu) * rsig * w.y + bb.y + xv.y;
        o.z = (z.z - mu) * rsig * w.z + bb.z + xv.z;
        o.w = (z.w - mu) * rsig * w.w + bb.w + xv.w;
        ((float4*)out)[i] = o;
    }
}

// ---------------- launch -----------------------------------------------------
extern "C" void kernel_launch(void* const* d_in, const int* in_sizes, int n_in,
                              void* d_out, int out_size)
{
    const float* x   = (const float*)d_in[0];
    const float* Wg  = (const float*)d_in[1];
    const float* bg  = (const float*)d_in[2];
    const float* Wt  = (const float*)d_in[3];
    const float* bt  = (const float*)d_in[4];
    const float* Wp  = (const float*)d_in[5];
    const float* bp  = (const float*)d_in[6];
    const float* Wz  = (const float*)d_in[7];
    const float* bz  = (const float*)d_in[8];
    const float* lnw = (const float*)d_in[9];
    const float* lnb = (const float*)d_in[10];
    float* out = (float*)d_out;

    cudaFuncSetAttribute(attn_kernel, cudaFuncAttributeMaxDynamicSharedMemorySize,
                         (int)sizeof(ASmem));
    cudaFuncSetAttribute(proj_mma, cudaFuncAttributeMaxDynamicSharedMemorySize,
                         GEMM_SMEM);
    cudaFuncSetAttribute(zgemm_mma, cudaFuncAttributeMaxDynamicSharedMemorySize,
                         ZG_SMEM);

    proj_mma<<<dim3(64, 12), 256, GEMM_SMEM>>>(x, Wg, bg, Wt, bt, Wp, bp);
    attn_kernel<<<dim3(32, 4), 256, sizeof(ASmem)>>>();
    zgemm_mma<<<dim3(64, 2, 4), 256, ZG_SMEM>>>(Wz, bz);
    stats_kernel<<<4, 128>>>();
    finalize_kernel<<<4096, 256>>>(x, lnw, lnb, out);
}

// round 8
// speedup vs baseline: 7.4995x; 1.0343x over previous
#include <cuda_runtime.h>
#include <cuda_fp16.h>
#include <math.h>
#include <stdint.h>

#define Bn   4
#define CINn 256
#define Fn   128
#define Nn   4096
#define EPSc 1e-5f

// ---------------- scratch (device globals: no allocation allowed) ----------
__device__ __half d_x16[(size_t)Bn * Nn * CINn];  // x transposed [b][n][c] fp16
__device__ __half d_w16[4 * 32768];               // Wg,Wt,Wp [128][256]; Wz [256][128]
__device__ __half d_t16[(size_t)Bn * Nn * Fn];    // theta, [b][n][f]
__device__ __half d_p16[(size_t)Bn * Nn * Fn];    // phi,   [b][n][f]
__device__ __half d_g16[(size_t)Bn * Fn * Nn];    // g,     [b][f][n]
__device__ __half d_y16[(size_t)Bn * Nn * Fn];    // y,     [b][n][f]
__device__ float  d_z[(size_t)Bn * CINn * Nn];    // pre-LN output [b][c][n]
__device__ float  d_part[2 * Bn * 128];           // per-tile (sum,sumsq) partials
__device__ float  d_stats[2 * Bn];                // per-batch (mu, rsig)

// ---------------- mma helpers ----------------------------------------------
__device__ __forceinline__ void mma16(float c[4],
        uint32_t a0, uint32_t a1, uint32_t a2, uint32_t a3,
        uint32_t b0, uint32_t b1) {
    asm volatile(
        "mma.sync.aligned.m16n8k16.row.col.f32.f16.f16.f32 "
        "{%0,%1,%2,%3}, {%4,%5,%6,%7}, {%8,%9}, {%0,%1,%2,%3};\n"
        : "+f"(c[0]), "+f"(c[1]), "+f"(c[2]), "+f"(c[3])
        : "r"(a0), "r"(a1), "r"(a2), "r"(a3), "r"(b0), "r"(b1));
}
__device__ __forceinline__ uint32_t ldu32(const __half* p) {
    return *(const uint32_t*)p;
}

// ============================================================================
// kernel 0a: convert the four weight matrices to fp16 (once per launch)
// ============================================================================
__global__ __launch_bounds__(256) void prep_w(
    const float* __restrict__ Wg, const float* __restrict__ Wt,
    const float* __restrict__ Wp, const float* __restrict__ Wz)
{
    const float* srcs[4] = {Wg, Wt, Wp, Wz};
    int stride = gridDim.x * blockDim.x;
    for (int i = blockIdx.x * blockDim.x + threadIdx.x; i < 4 * 8192; i += stride) {
        int w = i >> 13;        // matrix index (8192 float4 each)
        int e = i & 8191;
        float4 v = ((const float4*)srcs[w])[e];
        *(__half2*)&d_w16[(size_t)w * 32768 + e * 4]     = __floats2half2_rn(v.x, v.y);
        *(__half2*)&d_w16[(size_t)w * 32768 + e * 4 + 2] = __floats2half2_rn(v.z, v.w);
    }
}

// ============================================================================
// kernel 0b: transpose x [b][c][n] fp32 -> d_x16 [b][n][c] fp16
//   tile 64c x 32n, smem staged, coalesced both directions
// ============================================================================
__global__ __launch_bounds__(256) void xpose(const float* __restrict__ x)
{
    __shared__ float t[64][33];
    int b  = blockIdx.z;
    int c0 = blockIdx.y * 64;
    int n0 = blockIdx.x * 32;
    const float* X = x + ((size_t)b * CINn + c0) * Nn;
    int tid = threadIdx.x;
    int tn = tid & 31, tc = tid >> 5;

    #pragma unroll
    for (int cc = tc; cc < 64; cc += 8)
        t[cc][tn] = X[(size_t)cc * Nn + n0 + tn];
    __syncthreads();

    int lane = tid & 31, warp = tid >> 5;
    __half* out = d_x16 + ((size_t)b * Nn + n0) * CINn + c0;
    #pragma unroll
    for (int nn = warp; nn < 32; nn += 8) {
        float v0 = t[2 * lane][nn], v1 = t[2 * lane + 1][nn];
        *(__half2*)&out[(size_t)nn * CINn + 2 * lane] = __floats2half2_rn(v0, v1);
    }
}

// ============================================================================
// kernel 1: the three 1x1-conv GEMMs on fp16 mma, K=256 fully resident
//   out[m][n] = sum_k W[m][k] * x16[n][k] + bias[m]
//   Ws [128][264], Xs [64][264]: pitch 132 words = 4 mod 32 -> conflict-free
// ============================================================================
#define PW_PITCH 264
#define PROJ_SMEM ((128 + 64) * PW_PITCH * 2)

__global__ __launch_bounds__(256) void proj_mma(
    const float* __restrict__ bg, const float* __restrict__ bt,
    const float* __restrict__ bp)
{
    extern __shared__ char psm[];
    __half* Ws = (__half*)psm;                        // [128][264]
    __half* Xs = (__half*)(psm + 128 * PW_PITCH * 2); // [64][264]

    int pb   = blockIdx.y;
    int proj = pb % 3;
    int b    = pb / 3;
    const __half* Wm = d_w16 + (size_t)proj * 32768;
    const float* bias = (proj == 0) ? bg : (proj == 1 ? bt : bp);

    const __half* X16 = d_x16 + (size_t)b * Nn * CINn;
    int n0 = blockIdx.x * 64;

    int tid = threadIdx.x;
    int lane = tid & 31, warp = tid >> 5;
    int r = lane >> 2, cl = lane & 3;
    int qrow = warp * 16 + r;

    // fill W tile: pure fp16 copy [128][256]
    #pragma unroll
    for (int e = tid; e < 128 * 32; e += 256) {
        int m = e >> 5, c8 = (e & 31) * 8;
        *(uint4*)&Ws[m * PW_PITCH + c8] = *(const uint4*)&Wm[(size_t)m * 256 + c8];
    }
    // fill X tile: pure fp16 copy [64][256] from x16[n][c]
    #pragma unroll
    for (int e = tid; e < 64 * 32; e += 256) {
        int n = e >> 5, c8 = (e & 31) * 8;
        *(uint4*)&Xs[n * PW_PITCH + c8] =
            *(const uint4*)&X16[(size_t)(n0 + n) * CINn + c8];
    }
    __syncthreads();

    float acc[8][4];
    #pragma unroll
    for (int i = 0; i < 8; i++)
        #pragma unroll
        for (int j = 0; j < 4; j++) acc[i][j] = 0.f;

    #pragma unroll
    for (int kk = 0; kk < CINn; kk += 16) {
        uint32_t a0 = ldu32(&Ws[qrow       * PW_PITCH + kk + 2 * cl    ]);
        uint32_t a1 = ldu32(&Ws[(qrow + 8) * PW_PITCH + kk + 2 * cl    ]);
        uint32_t a2 = ldu32(&Ws[qrow       * PW_PITCH + kk + 2 * cl + 8]);
        uint32_t a3 = ldu32(&Ws[(qrow + 8) * PW_PITCH + kk + 2 * cl + 8]);
        #pragma unroll
        for (int nt = 0; nt < 8; nt++) {
            int nc = nt * 8 + r;
            uint32_t b0 = ldu32(&Xs[nc * PW_PITCH + kk + 2 * cl    ]);
            uint32_t b1 = ldu32(&Xs[nc * PW_PITCH + kk + 2 * cl + 8]);
            mma16(acc[nt], a0, a1, a2, a3, b0, b1);
        }
    }

    float bi0 = bias[qrow], bi1 = bias[qrow + 8];
    if (proj == 0) {
        __half* out = d_g16 + (size_t)b * Fn * Nn;
        #pragma unroll
        for (int nt = 0; nt < 8; nt++) {
            int nc = n0 + nt * 8 + 2 * cl;
            *(__half2*)&out[(size_t)qrow * Nn + nc] =
                __floats2half2_rn(acc[nt][0] + bi0, acc[nt][1] + bi0);
            *(__half2*)&out[(size_t)(qrow + 8) * Nn + nc] =
                __floats2half2_rn(acc[nt][2] + bi1, acc[nt][3] + bi1);
        }
    } else {
        __half* out = (proj == 1 ? d_t16 : d_p16) + (size_t)b * Nn * Fn;
        #pragma unroll
        for (int nt = 0; nt < 8; nt++) {
            int nc = n0 + nt * 8 + 2 * cl;
            out[(size_t)nc       * Fn + qrow    ] = __float2half_rn(acc[nt][0] + bi0);
            out[(size_t)(nc + 1) * Fn + qrow    ] = __float2half_rn(acc[nt][1] + bi0);
            out[(size_t)nc       * Fn + qrow + 8] = __float2half_rn(acc[nt][2] + bi1);
            out[(size_t)(nc + 1) * Fn + qrow + 8] = __float2half_rn(acc[nt][3] + bi1);
        }
    }
}

// ============================================================================
// kernel 2: fused flash attention on fp16 mma (m16n8k16), fp32 accumulate
// ============================================================================
struct ASmem {
    __half Th[128][136];  // theta [q][f]
    __half Ph[64][136];   // phi   [m][f]
    __half Gs[Fn][72];    // g     [f][m]
    __half Ps[128][72];   // probs [q][m]
};

__global__ __launch_bounds__(256, 1) void attn_kernel()
{
    extern __shared__ char smraw[];
    ASmem& sm = *reinterpret_cast<ASmem*>(smraw);

    int b  = blockIdx.y;
    int q0 = blockIdx.x * 128;
    const __half* t16 = d_t16 + (size_t)b * Nn * Fn;
    const __half* p16 = d_p16 + (size_t)b * Nn * Fn;
    const __half* g16 = d_g16 + (size_t)b * Fn * Nn;

    int tid  = threadIdx.x;
    int lane = tid & 31, warp = tid >> 5;
    int r = lane >> 2, cl = lane & 3;
    int qrow = warp * 16 + r;

    #pragma unroll
    for (int e = tid; e < 128 * 16; e += 256) {
        int q = e >> 4, c8 = (e & 15) * 8;
        *(uint4*)&sm.Th[q][c8] = *(const uint4*)&t16[(size_t)(q0 + q) * Fn + c8];
    }

    float oc[16][4];
    #pragma unroll
    for (int i = 0; i < 16; i++)
        #pragma unroll
        for (int j = 0; j < 4; j++) oc[i][j] = 0.f;

    float m0_ = -3.0e38f, m1_ = -3.0e38f;
    float l0_ = 0.f,      l1_ = 0.f;

    __syncthreads();

    for (int mb = 0; mb < Nn; mb += 64) {
        #pragma unroll
        for (int e = tid; e < 64 * 16; e += 256) {
            int m = e >> 4, c8 = (e & 15) * 8;
            *(uint4*)&sm.Ph[m][c8] = *(const uint4*)&p16[(size_t)(mb + m) * Fn + c8];
        }
        #pragma unroll
        for (int e = tid; e < 128 * 8; e += 256) {
            int f = e >> 3, c8 = (e & 7) * 8;
            *(uint4*)&sm.Gs[f][c8] = *(const uint4*)&g16[(size_t)f * Nn + mb + c8];
        }
        __syncthreads();

        float sc[8][4];
        #pragma unroll
        for (int i = 0; i < 8; i++)
            #pragma unroll
            for (int j = 0; j < 4; j++) sc[i][j] = 0.f;

        #pragma unroll
        for (int kk = 0; kk < Fn; kk += 16) {
            uint32_t a0 = ldu32(&sm.Th[qrow    ][kk + 2 * cl    ]);
            uint32_t a1 = ldu32(&sm.Th[qrow + 8][kk + 2 * cl    ]);
            uint32_t a2 = ldu32(&sm.Th[qrow    ][kk + 2 * cl + 8]);
            uint32_t a3 = ldu32(&sm.Th[qrow + 8][kk + 2 * cl + 8]);
            #pragma unroll
            for (int nt = 0; nt < 8; nt++) {
                int mc = nt * 8 + r;
                uint32_t b0 = ldu32(&sm.Ph[mc][kk + 2 * cl    ]);
                uint32_t b1 = ldu32(&sm.Ph[mc][kk + 2 * cl + 8]);
                mma16(sc[nt], a0, a1, a2, a3, b0, b1);
            }
        }

        float mx0 = -3.0e38f, mx1 = -3.0e38f;
        #pragma unroll
        for (int nt = 0; nt < 8; nt++) {
            mx0 = fmaxf(mx0, fmaxf(sc[nt][0], sc[nt][1]));
            mx1 = fmaxf(mx1, fmaxf(sc[nt][2], sc[nt][3]));
        }
        #pragma unroll
        for (int o = 1; o < 4; o <<= 1) {
            mx0 = fmaxf(mx0, __shfl_xor_sync(0xffffffffu, mx0, o));
            mx1 = fmaxf(mx1, __shfl_xor_sync(0xffffffffu, mx1, o));
        }
        float nm0 = fmaxf(m0_, mx0), nm1 = fmaxf(m1_, mx1);
        float al0 = __expf(m0_ - nm0), al1 = __expf(m1_ - nm1);
        m0_ = nm0; m1_ = nm1;

        float rs0 = 0.f, rs1 = 0.f;
        #pragma unroll
        for (int nt = 0; nt < 8; nt++) {
            float p0 = __expf(sc[nt][0] - nm0);
            float p1 = __expf(sc[nt][1] - nm0);
            float p2 = __expf(sc[nt][2] - nm1);
            float p3 = __expf(sc[nt][3] - nm1);
            rs0 += p0 + p1; rs1 += p2 + p3;
            int mc = nt * 8 + 2 * cl;
            *(__half2*)&sm.Ps[qrow    ][mc] = __floats2half2_rn(p0, p1);
            *(__half2*)&sm.Ps[qrow + 8][mc] = __floats2half2_rn(p2, p3);
        }
        #pragma unroll
        for (int o = 1; o < 4; o <<= 1) {
            rs0 += __shfl_xor_sync(0xffffffffu, rs0, o);
            rs1 += __shfl_xor_sync(0xffffffffu, rs1, o);
        }
        l0_ = l0_ * al0 + rs0;
        l1_ = l1_ * al1 + rs1;

        #pragma unroll
        for (int ft = 0; ft < 16; ft++) {
            oc[ft][0] *= al0; oc[ft][1] *= al0;
            oc[ft][2] *= al1; oc[ft][3] *= al1;
        }

        __syncwarp();

        #pragma unroll
        for (int mk = 0; mk < 64; mk += 16) {
            uint32_t a0 = ldu32(&sm.Ps[qrow    ][mk + 2 * cl    ]);
            uint32_t a1 = ldu32(&sm.Ps[qrow + 8][mk + 2 * cl    ]);
            uint32_t a2 = ldu32(&sm.Ps[qrow    ][mk + 2 * cl + 8]);
            uint32_t a3 = ldu32(&sm.Ps[qrow + 8][mk + 2 * cl + 8]);
            #pragma unroll
            for (int ft = 0; ft < 16; ft++) {
                int fb = ft * 8 + r;
                uint32_t b0 = ldu32(&sm.Gs[fb][mk + 2 * cl    ]);
                uint32_t b1 = ldu32(&sm.Gs[fb][mk + 2 * cl + 8]);
                mma16(oc[ft], a0, a1, a2, a3, b0, b1);
            }
        }
        __syncthreads();
    }

    float li0 = 1.0f / l0_, li1 = 1.0f / l1_;
    __half* yb = d_y16 + ((size_t)b * Nn + q0) * Fn;
    #pragma unroll
    for (int ft = 0; ft < 16; ft++) {
        int fb = ft * 8 + 2 * cl;
        *(__half2*)&yb[(size_t)qrow * Fn + fb] =
            __floats2half2_rn(oc[ft][0] * li0, oc[ft][1] * li0);
        *(__half2*)&yb[(size_t)(qrow + 8) * Fn + fb] =
            __floats2half2_rn(oc[ft][2] * li1, oc[ft][3] * li1);
    }
}

// ============================================================================
// kernel 3: z = Wz @ y + bz on fp16 mma (single K pass), LN partials fused
// ============================================================================
#define ZW_PITCH 136
#define ZY_PITCH 136
#define ZG_SMEM (128 * ZW_PITCH * 2 + 64 * ZY_PITCH * 2)

__global__ __launch_bounds__(256) void zgemm_mma(const float* __restrict__ bz)
{
    extern __shared__ char zsm[];
    __half* Ws = (__half*)zsm;                        // [128][136]
    __half* Ys = (__half*)(zsm + 128 * ZW_PITCH * 2); // [64][136]

    int b  = blockIdx.z;
    int m0 = blockIdx.y * 128;
    int n0 = blockIdx.x * 64;
    const __half* W16z = d_w16 + (size_t)3 * 32768;   // [256][128]
    const __half* Y16 = d_y16 + (size_t)b * Nn * Fn;
    float* Z = d_z + (size_t)b * CINn * Nn;

    int tid = threadIdx.x;
    int lane = tid & 31, warp = tid >> 5;
    int r = lane >> 2, cl = lane & 3;
    int qrow = warp * 16 + r;

    // fill A: pure fp16 copy
    #pragma unroll
    for (int e = tid; e < 128 * 16; e += 256) {
        int m = e >> 4, c8 = (e & 15) * 8;
        *(uint4*)&Ws[m * ZW_PITCH + c8] =
            *(const uint4*)&W16z[(size_t)(m0 + m) * Fn + c8];
    }
    // fill B (y16 copy)
    #pragma unroll
    for (int e = tid; e < 64 * 16; e += 256) {
        int n = e >> 4, c8 = (e & 15) * 8;
        *(uint4*)&Ys[n * ZY_PITCH + c8] = *(const uint4*)&Y16[(size_t)(n0 + n) * Fn + c8];
    }
    __syncthreads();

    float acc[8][4];
    #pragma unroll
    for (int i = 0; i < 8; i++)
        #pragma unroll
        for (int j = 0; j < 4; j++) acc[i][j] = 0.f;

    #pragma unroll
    for (int kk = 0; kk < Fn; kk += 16) {
        uint32_t a0 = ldu32(&Ws[qrow       * ZW_PITCH + kk + 2 * cl    ]);
        uint32_t a1 = ldu32(&Ws[(qrow + 8) * ZW_PITCH + kk + 2 * cl    ]);
        uint32_t a2 = ldu32(&Ws[qrow       * ZW_PITCH + kk + 2 * cl + 8]);
        uint32_t a3 = ldu32(&Ws[(qrow + 8) * ZW_PITCH + kk + 2 * cl + 8]);
        #pragma unroll
        for (int nt = 0; nt < 8; nt++) {
            int nc = nt * 8 + r;
            uint32_t b0 = ldu32(&Ys[nc * ZY_PITCH + kk + 2 * cl    ]);
            uint32_t b1 = ldu32(&Ys[nc * ZY_PITCH + kk + 2 * cl + 8]);
            mma16(acc[nt], a0, a1, a2, a3, b0, b1);
        }
    }
    __syncthreads();

    float bi0 = bz[m0 + qrow], bi1 = bz[m0 + qrow + 8];
    float lsum = 0.f, lsq = 0.f;
    #pragma unroll
    for (int nt = 0; nt < 8; nt++) {
        int nc = n0 + nt * 8 + 2 * cl;
        float v0 = acc[nt][0] + bi0, v1 = acc[nt][1] + bi0;
        float v2 = acc[nt][2] + bi1, v3 = acc[nt][3] + bi1;
        *(float2*)&Z[(size_t)(m0 + qrow) * Nn + nc]     = make_float2(v0, v1);
        *(float2*)&Z[(size_t)(m0 + qrow + 8) * Nn + nc] = make_float2(v2, v3);
        lsum += v0 + v1 + v2 + v3;
        lsq  += v0 * v0 + v1 * v1 + v2 * v2 + v3 * v3;
    }

    float* rs = (float*)zsm;          // safe: all smem reads done
    float* rq = rs + 256;
    rs[tid] = lsum; rq[tid] = lsq;
    __syncthreads();
    #pragma unroll
    for (int s = 128; s > 0; s >>= 1) {
        if (tid < s) { rs[tid] += rs[tid + s]; rq[tid] += rq[tid + s]; }
        __syncthreads();
    }
    if (tid == 0) {
        int idx = b * 128 + blockIdx.y * 64 + blockIdx.x;
        d_part[2 * idx]     = rs[0];
        d_part[2 * idx + 1] = rq[0];
    }
}

// ---------------- kernel 4: per-batch mean / rsig ---------------------------
__global__ __launch_bounds__(128) void stats_kernel()
{
    int b = blockIdx.x;
    int tid = threadIdx.x;
    __shared__ float rs[128], rq[128];
    int idx = b * 128 + tid;
    rs[tid] = d_part[2 * idx];
    rq[tid] = d_part[2 * idx + 1];
    __syncthreads();
    #pragma unroll
    for (int s = 64; s > 0; s >>= 1) {
        if (tid < s) { rs[tid] += rs[tid + s]; rq[tid] += rq[tid + s]; }
        __syncthreads();
    }
    if (tid == 0) {
        float inv = 1.0f / ((float)CINn * (float)Nn);
        float mu  = rs[0] * inv;
        float var = rq[0] * inv - mu * mu;
        d_stats[2 * b]     = mu;
        d_stats[2 * b + 1] = rsqrtf(var + EPSc);
    }
}

// ---------------- kernel 5: LN affine + residual ----------------------------
__global__ __launch_bounds__(256) void finalize_kernel(
    const float* __restrict__ x, const float* __restrict__ lw,
    const float* __restrict__ lb, float* __restrict__ out)
{
    const int per_b4 = CINn * Nn / 4;
    const int tot4   = Bn * per_b4;
    for (int i = blockIdx.x * blockDim.x + threadIdx.x; i < tot4;
         i += gridDim.x * blockDim.x) {
        int b = i / per_b4;
        int r = i - b * per_b4;
        float mu   = d_stats[2 * b];
        float rsig = d_stats[2 * b + 1];
        float4 z  = ((const float4*)d_z)[i];
        float4 xv = ((const float4*)x)[i];
        float4 w  = ((const float4*)lw)[r];
        float4 bb = ((const float4*)lb)[r];
        float4 o;
        o.x = (z.x - mu) * rsig * w.x + bb.x + xv.x;
        o.y = (z.y - mu) * rsig * w.y + bb.y + xv.y;
        o.z = (z.z - mu) * rsig * w.z + bb.z + xv.z;
        o.w = (z.w - mu) * rsig * w.w + bb.w + xv.w;
        ((float4*)out)[i] = o;
    }
}

// ---------------- launch -----------------------------------------------------
extern "C" void kernel_launch(void* const* d_in, const int* in_sizes, int n_in,
                              void* d_out, int out_size)
{
    const float* x   = (const float*)d_in[0];
    const float* Wg  = (const float*)d_in[1];
    const float* bg  = (const float*)d_in[2];
    const float* Wt  = (const float*)d_in[3];
    const float* bt  = (const float*)d_in[4];
    const float* Wp  = (const float*)d_in[5];
    const float* bp  = (const float*)d_in[6];
    const float* Wz  = (const float*)d_in[7];
    const float* bz  = (const float*)d_in[8];
    const float* lnw = (const float*)d_in[9];
    const float* lnb = (const float*)d_in[10];
    float* out = (float*)d_out;

    cudaFuncSetAttribute(attn_kernel, cudaFuncAttributeMaxDynamicSharedMemorySize,
                         (int)sizeof(ASmem));
    cudaFuncSetAttribute(proj_mma, cudaFuncAttributeMaxDynamicSharedMemorySize,
                         PROJ_SMEM);
    cudaFuncSetAttribute(zgemm_mma, cudaFuncAttributeMaxDynamicSharedMemorySize,
                         ZG_SMEM);

    prep_w<<<128, 256>>>(Wg, Wt, Wp, Wz);
    xpose<<<dim3(128, 4, 4), 256>>>(x);
    proj_mma<<<dim3(64, 12), 256, PROJ_SMEM>>>(bg, bt, bp);
    attn_kernel<<<dim3(32, 4), 256, sizeof(ASmem)>>>();
    zgemm_mma<<<dim3(64, 2, 4), 256, ZG_SMEM>>>(bz);
    stats_kernel<<<4, 128>>>();
    finalize_kernel<<<4096, 256>>>(x, lnw, lnb, out);
}

// round 10
// speedup vs baseline: 9.1137x; 1.2152x over previous
#include <cuda_runtime.h>
#include <cuda_fp16.h>
#include <math.h>
#include <stdint.h>

#define Bn   4
#define CINn 256
#define Fn   128
#define Nn   4096
#define EPSc 1e-5f

// ---------------- scratch (device globals: no allocation allowed) ----------
__device__ __half d_x16[(size_t)Bn * Nn * CINn];  // x transposed [b][n][c] fp16
__device__ __half d_w16[4 * 32768];               // Wg,Wt,Wp [128][256]; Wz [256][128]
__device__ __half d_t16[(size_t)Bn * Nn * Fn];    // theta, [b][n][f]
__device__ __half d_p16[(size_t)Bn * Nn * Fn];    // phi,   [b][n][f]
__device__ __half d_g16[(size_t)Bn * Fn * Nn];    // g,     [b][f][n]
__device__ __half d_y16[(size_t)Bn * Nn * Fn];    // y,     [b][n][f]
__device__ float  d_z[(size_t)Bn * CINn * Nn];    // pre-LN output [b][c][n]
__device__ float  d_part[2 * Bn * 128];           // per-tile (sum,sumsq) partials
__device__ float  d_stats[2 * Bn];                // per-batch (mu, rsig)

// ---------------- helpers ---------------------------------------------------
__device__ __forceinline__ void mma16(float c[4],
        uint32_t a0, uint32_t a1, uint32_t a2, uint32_t a3,
        uint32_t b0, uint32_t b1) {
    asm volatile(
        "mma.sync.aligned.m16n8k16.row.col.f32.f16.f16.f32 "
        "{%0,%1,%2,%3}, {%4,%5,%6,%7}, {%8,%9}, {%0,%1,%2,%3};\n"
        : "+f"(c[0]), "+f"(c[1]), "+f"(c[2]), "+f"(c[3])
        : "r"(a0), "r"(a1), "r"(a2), "r"(a3), "r"(b0), "r"(b1));
}
__device__ __forceinline__ uint32_t ldu32(const __half* p) {
    return *(const uint32_t*)p;
}
__device__ __forceinline__ uint32_t packh2(float a, float b) {
    __half2 h = __floats2half2_rn(a, b);
    return *(uint32_t*)&h;
}
__device__ __forceinline__ void cpa16(uint32_t dst, const void* src) {
    asm volatile("cp.async.cg.shared.global [%0], [%1], 16;" :: "r"(dst), "l"(src));
}
#define CP_COMMIT() asm volatile("cp.async.commit_group;")
#define CP_WAIT1()  asm volatile("cp.async.wait_group 1;")
__device__ __forceinline__ uint32_t s2u(const void* p) {
    return (uint32_t)__cvta_generic_to_shared(p);
}

// ============================================================================
// kernel 0a: convert the four weight matrices to fp16 (once per launch)
// ============================================================================
__global__ __launch_bounds__(256) void prep_w(
    const float* __restrict__ Wg, const float* __restrict__ Wt,
    const float* __restrict__ Wp, const float* __restrict__ Wz)
{
    const float* srcs[4] = {Wg, Wt, Wp, Wz};
    int stride = gridDim.x * blockDim.x;
    for (int i = blockIdx.x * blockDim.x + threadIdx.x; i < 4 * 8192; i += stride) {
        int w = i >> 13;
        int e = i & 8191;
        float4 v = ((const float4*)srcs[w])[e];
        *(__half2*)&d_w16[(size_t)w * 32768 + e * 4]     = __floats2half2_rn(v.x, v.y);
        *(__half2*)&d_w16[(size_t)w * 32768 + e * 4 + 2] = __floats2half2_rn(v.z, v.w);
    }
}

// ============================================================================
// kernel 0b: transpose x [b][c][n] fp32 -> d_x16 [b][n][c] fp16
// ============================================================================
__global__ __launch_bounds__(256) void xpose(const float* __restrict__ x)
{
    __shared__ float t[64][33];
    int b  = blockIdx.z;
    int c0 = blockIdx.y * 64;
    int n0 = blockIdx.x * 32;
    const float* X = x + ((size_t)b * CINn + c0) * Nn;
    int tid = threadIdx.x;
    int tn = tid & 31, tc = tid >> 5;

    #pragma unroll
    for (int cc = tc; cc < 64; cc += 8)
        t[cc][tn] = X[(size_t)cc * Nn + n0 + tn];
    __syncthreads();

    int lane = tid & 31, warp = tid >> 5;
    __half* out = d_x16 + ((size_t)b * Nn + n0) * CINn + c0;
    #pragma unroll
    for (int nn = warp; nn < 32; nn += 8) {
        float v0 = t[2 * lane][nn], v1 = t[2 * lane + 1][nn];
        *(__half2*)&out[(size_t)nn * CINn + 2 * lane] = __floats2half2_rn(v0, v1);
    }
}

// ============================================================================
// kernel 1: the three 1x1-conv GEMMs on fp16 mma, K=256 fully resident
// ============================================================================
#define PW_PITCH 264
#define PROJ_SMEM ((128 + 64) * PW_PITCH * 2)

__global__ __launch_bounds__(256) void proj_mma(
    const float* __restrict__ bg, const float* __restrict__ bt,
    const float* __restrict__ bp)
{
    extern __shared__ char psm[];
    __half* Ws = (__half*)psm;                        // [128][264]
    __half* Xs = (__half*)(psm + 128 * PW_PITCH * 2); // [64][264]

    int pb   = blockIdx.y;
    int proj = pb % 3;
    int b    = pb / 3;
    const __half* Wm = d_w16 + (size_t)proj * 32768;
    const float* bias = (proj == 0) ? bg : (proj == 1 ? bt : bp);

    const __half* X16 = d_x16 + (size_t)b * Nn * CINn;
    int n0 = blockIdx.x * 64;

    int tid = threadIdx.x;
    int lane = tid & 31, warp = tid >> 5;
    int r = lane >> 2, cl = lane & 3;
    int qrow = warp * 16 + r;

    #pragma unroll
    for (int e = tid; e < 128 * 32; e += 256) {
        int m = e >> 5, c8 = (e & 31) * 8;
        *(uint4*)&Ws[m * PW_PITCH + c8] = *(const uint4*)&Wm[(size_t)m * 256 + c8];
    }
    #pragma unroll
    for (int e = tid; e < 64 * 32; e += 256) {
        int n = e >> 5, c8 = (e & 31) * 8;
        *(uint4*)&Xs[n * PW_PITCH + c8] =
            *(const uint4*)&X16[(size_t)(n0 + n) * CINn + c8];
    }
    __syncthreads();

    float acc[8][4];
    #pragma unroll
    for (int i = 0; i < 8; i++)
        #pragma unroll
        for (int j = 0; j < 4; j++) acc[i][j] = 0.f;

    #pragma unroll
    for (int kk = 0; kk < CINn; kk += 16) {
        uint32_t a0 = ldu32(&Ws[qrow       * PW_PITCH + kk + 2 * cl    ]);
        uint32_t a1 = ldu32(&Ws[(qrow + 8) * PW_PITCH + kk + 2 * cl    ]);
        uint32_t a2 = ldu32(&Ws[qrow       * PW_PITCH + kk + 2 * cl + 8]);
        uint32_t a3 = ldu32(&Ws[(qrow + 8) * PW_PITCH + kk + 2 * cl + 8]);
        #pragma unroll
        for (int nt = 0; nt < 8; nt++) {
            int nc = nt * 8 + r;
            uint32_t b0 = ldu32(&Xs[nc * PW_PITCH + kk + 2 * cl    ]);
            uint32_t b1 = ldu32(&Xs[nc * PW_PITCH + kk + 2 * cl + 8]);
            mma16(acc[nt], a0, a1, a2, a3, b0, b1);
        }
    }

    float bi0 = bias[qrow], bi1 = bias[qrow + 8];
    if (proj == 0) {
        __half* out = d_g16 + (size_t)b * Fn * Nn;
        #pragma unroll
        for (int nt = 0; nt < 8; nt++) {
            int nc = n0 + nt * 8 + 2 * cl;
            *(__half2*)&out[(size_t)qrow * Nn + nc] =
                __floats2half2_rn(acc[nt][0] + bi0, acc[nt][1] + bi0);
            *(__half2*)&out[(size_t)(qrow + 8) * Nn + nc] =
                __floats2half2_rn(acc[nt][2] + bi1, acc[nt][3] + bi1);
        }
    } else {
        __half* out = (proj == 1 ? d_t16 : d_p16) + (size_t)b * Nn * Fn;
        #pragma unroll
        for (int nt = 0; nt < 8; nt++) {
            int nc = n0 + nt * 8 + 2 * cl;
            out[(size_t)nc       * Fn + qrow    ] = __float2half_rn(acc[nt][0] + bi0);
            out[(size_t)(nc + 1) * Fn + qrow    ] = __float2half_rn(acc[nt][1] + bi0);
            out[(size_t)nc       * Fn + qrow + 8] = __float2half_rn(acc[nt][2] + bi1);
            out[(size_t)(nc + 1) * Fn + qrow + 8] = __float2half_rn(acc[nt][3] + bi1);
        }
    }
}

// ============================================================================
// kernel 2: fused flash attention, fp16 mma, cp.async 3-stage pipeline,
//   theta + P resident in registers (no Th / Ps smem, 1 barrier per chunk)
// ============================================================================
#define PH_HALVES (64 * 136)           // phi stage  [m][f], pitch 136
#define GS_HALVES (128 * 72)           // g   stage  [f][m], pitch 72
#define STAGE_HALVES (PH_HALVES + GS_HALVES)
#define ATTN_SMEM (3 * STAGE_HALVES * 2)

__global__ __launch_bounds__(256, 1) void attn_kernel()
{
    extern __shared__ __half sh[];

    int b  = blockIdx.y;
    int q0 = blockIdx.x * 128;
    const __half* t16 = d_t16 + (size_t)b * Nn * Fn;
    const __half* p16 = d_p16 + (size_t)b * Nn * Fn;
    const __half* g16 = d_g16 + (size_t)b * Fn * Nn;

    int tid  = threadIdx.x;
    int lane = tid & 31, warp = tid >> 5;
    int r = lane >> 2, cl = lane & 3;
    int qrow = warp * 16 + r;

    // ---- theta fragments -> registers (one-time gmem read) ----
    uint32_t th[8][4];
    {
        const __half* t0 = &t16[(size_t)(q0 + qrow) * Fn];
        const __half* t1 = &t16[(size_t)(q0 + qrow + 8) * Fn];
        #pragma unroll
        for (int kk = 0; kk < 8; kk++) {
            th[kk][0] = ldu32(&t0[kk * 16 + 2 * cl]);
            th[kk][1] = ldu32(&t1[kk * 16 + 2 * cl]);
            th[kk][2] = ldu32(&t0[kk * 16 + 2 * cl + 8]);
            th[kk][3] = ldu32(&t1[kk * 16 + 2 * cl + 8]);
        }
    }

    float oc[16][4];
    #pragma unroll
    for (int i = 0; i < 16; i++)
        #pragma unroll
        for (int j = 0; j < 4; j++) oc[i][j] = 0.f;

    float m0_ = -3.0e38f, m1_ = -3.0e38f;
    float l0_ = 0.f,      l1_ = 0.f;

    // ---- cp.async chunk issue (all 256 threads) ----
    auto issue = [&](int mb, int s) {
        __half* ph = sh + s * STAGE_HALVES;
        __half* gs = ph + PH_HALVES;
        #pragma unroll
        for (int i = 0; i < 4; i++) {
            int e = tid + i * 256;
            int m = e >> 4, c8 = (e & 15) * 8;
            cpa16(s2u(&ph[m * 136 + c8]), &p16[(size_t)(mb + m) * Fn + c8]);
        }
        #pragma unroll
        for (int i = 0; i < 4; i++) {
            int e = tid + i * 256;
            int f = e >> 3, c8 = (e & 7) * 8;
            cpa16(s2u(&gs[f * 72 + c8]), &g16[(size_t)f * Nn + mb + c8]);
        }
    };

    // prologue: stages 0 and 1 in flight
    issue(0, 0);  CP_COMMIT();
    issue(64, 1); CP_COMMIT();

    for (int ic = 0; ic < 64; ic++) {
        CP_WAIT1();
        __syncthreads();
        if (ic + 2 < 64) issue((ic + 2) * 64, (ic + 2) % 3);
        CP_COMMIT();

        const __half* ph = sh + (ic % 3) * STAGE_HALVES;
        const __half* gs = ph + PH_HALVES;

        // ---- S = theta phi^T : 16q x 64m ----
        float sc[8][4];
        #pragma unroll
        for (int i = 0; i < 8; i++)
            #pragma unroll
            for (int j = 0; j < 4; j++) sc[i][j] = 0.f;

        #pragma unroll
        for (int kk = 0; kk < 8; kk++) {
            #pragma unroll
            for (int nt = 0; nt < 8; nt++) {
                const __half* pr = &ph[(nt * 8 + r) * 136 + kk * 16 + 2 * cl];
                mma16(sc[nt], th[kk][0], th[kk][1], th[kk][2], th[kk][3],
                      ldu32(pr), ldu32(pr + 8));
            }
        }

        // ---- online softmax (warp-local, all in registers) ----
        float mx0 = -3.0e38f, mx1 = -3.0e38f;
        #pragma unroll
        for (int nt = 0; nt < 8; nt++) {
            mx0 = fmaxf(mx0, fmaxf(sc[nt][0], sc[nt][1]));
            mx1 = fmaxf(mx1, fmaxf(sc[nt][2], sc[nt][3]));
        }
        #pragma unroll
        for (int o = 1; o < 4; o <<= 1) {
            mx0 = fmaxf(mx0, __shfl_xor_sync(0xffffffffu, mx0, o));
            mx1 = fmaxf(mx1, __shfl_xor_sync(0xffffffffu, mx1, o));
        }
        float nm0 = fmaxf(m0_, mx0), nm1 = fmaxf(m1_, mx1);
        float al0 = __expf(m0_ - nm0), al1 = __expf(m1_ - nm1);
        m0_ = nm0; m1_ = nm1;

        uint32_t pp[8], pq[8];
        float rs0 = 0.f, rs1 = 0.f;
        #pragma unroll
        for (int nt = 0; nt < 8; nt++) {
            float p0 = __expf(sc[nt][0] - nm0);
            float p1 = __expf(sc[nt][1] - nm0);
            float p2 = __expf(sc[nt][2] - nm1);
            float p3 = __expf(sc[nt][3] - nm1);
            rs0 += p0 + p1; rs1 += p2 + p3;
            pp[nt] = packh2(p0, p1);
            pq[nt] = packh2(p2, p3);
        }
        #pragma unroll
        for (int o = 1; o < 4; o <<= 1) {
            rs0 += __shfl_xor_sync(0xffffffffu, rs0, o);
            rs1 += __shfl_xor_sync(0xffffffffu, rs1, o);
        }
        l0_ = l0_ * al0 + rs0;
        l1_ = l1_ * al1 + rs1;

        #pragma unroll
        for (int ft = 0; ft < 16; ft++) {
            oc[ft][0] *= al0; oc[ft][1] *= al0;
            oc[ft][2] *= al1; oc[ft][3] *= al1;
        }

        // ---- O += P G^T : P fragments direct from registers ----
        #pragma unroll
        for (int j = 0; j < 4; j++) {
            uint32_t a0 = pp[2 * j], a1 = pq[2 * j];
            uint32_t a2 = pp[2 * j + 1], a3 = pq[2 * j + 1];
            #pragma unroll
            for (int ft = 0; ft < 16; ft++) {
                const __half* gr = &gs[(ft * 8 + r) * 72 + j * 16 + 2 * cl];
                mma16(oc[ft], a0, a1, a2, a3, ldu32(gr), ldu32(gr + 8));
            }
        }
    }

    // ---- epilogue: normalize, write y [n][f] fp16 straight from registers ----
    float li0 = 1.0f / l0_, li1 = 1.0f / l1_;
    __half* yb = d_y16 + ((size_t)b * Nn + q0) * Fn;
    #pragma unroll
    for (int ft = 0; ft < 16; ft++) {
        int fb = ft * 8 + 2 * cl;
        *(__half2*)&yb[(size_t)qrow * Fn + fb] =
            __floats2half2_rn(oc[ft][0] * li0, oc[ft][1] * li0);
        *(__half2*)&yb[(size_t)(qrow + 8) * Fn + fb] =
            __floats2half2_rn(oc[ft][2] * li1, oc[ft][3] * li1);
    }
}

// ============================================================================
// kernel 3: z = Wz @ y + bz on fp16 mma (single K pass), LN partials fused
// ============================================================================
#define ZW_PITCH 136
#define ZY_PITCH 136
#define ZG_SMEM (128 * ZW_PITCH * 2 + 64 * ZY_PITCH * 2)

__global__ __launch_bounds__(256) void zgemm_mma(const float* __restrict__ bz)
{
    extern __shared__ char zsm[];
    __half* Ws = (__half*)zsm;                        // [128][136]
    __half* Ys = (__half*)(zsm + 128 * ZW_PITCH * 2); // [64][136]

    int b  = blockIdx.z;
    int m0 = blockIdx.y * 128;
    int n0 = blockIdx.x * 64;
    const __half* W16z = d_w16 + (size_t)3 * 32768;   // [256][128]
    const __half* Y16 = d_y16 + (size_t)b * Nn * Fn;
    float* Z = d_z + (size_t)b * CINn * Nn;

    int tid = threadIdx.x;
    int lane = tid & 31, warp = tid >> 5;
    int r = lane >> 2, cl = lane & 3;
    int qrow = warp * 16 + r;

    #pragma unroll
    for (int e = tid; e < 128 * 16; e += 256) {
        int m = e >> 4, c8 = (e & 15) * 8;
        *(uint4*)&Ws[m * ZW_PITCH + c8] =
            *(const uint4*)&W16z[(size_t)(m0 + m) * Fn + c8];
    }
    #pragma unroll
    for (int e = tid; e < 64 * 16; e += 256) {
        int n = e >> 4, c8 = (e & 15) * 8;
        *(uint4*)&Ys[n * ZY_PITCH + c8] = *(const uint4*)&Y16[(size_t)(n0 + n) * Fn + c8];
    }
    __syncthreads();

    float acc[8][4];
    #pragma unroll
    for (int i = 0; i < 8; i++)
        #pragma unroll
        for (int j = 0; j < 4; j++) acc[i][j] = 0.f;

    #pragma unroll
    for (int kk = 0; kk < Fn; kk += 16) {
        uint32_t a0 = ldu32(&Ws[qrow       * ZW_PITCH + kk + 2 * cl    ]);
        uint32_t a1 = ldu32(&Ws[(qrow + 8) * ZW_PITCH + kk + 2 * cl    ]);
        uint32_t a2 = ldu32(&Ws[qrow       * ZW_PITCH + kk + 2 * cl + 8]);
        uint32_t a3 = ldu32(&Ws[(qrow + 8) * ZW_PITCH + kk + 2 * cl + 8]);
        #pragma unroll
        for (int nt = 0; nt < 8; nt++) {
            int nc = nt * 8 + r;
            uint32_t b0 = ldu32(&Ys[nc * ZY_PITCH + kk + 2 * cl    ]);
            uint32_t b1 = ldu32(&Ys[nc * ZY_PITCH + kk + 2 * cl + 8]);
            mma16(acc[nt], a0, a1, a2, a3, b0, b1);
        }
    }
    __syncthreads();

    float bi0 = bz[m0 + qrow], bi1 = bz[m0 + qrow + 8];
    float lsum = 0.f, lsq = 0.f;
    #pragma unroll
    for (int nt = 0; nt < 8; nt++) {
        int nc = n0 + nt * 8 + 2 * cl;
        float v0 = acc[nt][0] + bi0, v1 = acc[nt][1] + bi0;
        float v2 = acc[nt][2] + bi1, v3 = acc[nt][3] + bi1;
        *(float2*)&Z[(size_t)(m0 + qrow) * Nn + nc]     = make_float2(v0, v1);
        *(float2*)&Z[(size_t)(m0 + qrow + 8) * Nn + nc] = make_float2(v2, v3);
        lsum += v0 + v1 + v2 + v3;
        lsq  += v0 * v0 + v1 * v1 + v2 * v2 + v3 * v3;
    }

    float* rs = (float*)zsm;
    float* rq = rs + 256;
    rs[tid] = lsum; rq[tid] = lsq;
    __syncthreads();
    #pragma unroll
    for (int s = 128; s > 0; s >>= 1) {
        if (tid < s) { rs[tid] += rs[tid + s]; rq[tid] += rq[tid + s]; }
        __syncthreads();
    }
    if (tid == 0) {
        int idx = b * 128 + blockIdx.y * 64 + blockIdx.x;
        d_part[2 * idx]     = rs[0];
        d_part[2 * idx + 1] = rq[0];
    }
}

// ---------------- kernel 4: per-batch mean / rsig ---------------------------
__global__ __launch_bounds__(128) void stats_kernel()
{
    int b = blockIdx.x;
    int tid = threadIdx.x;
    __shared__ float rs[128], rq[128];
    int idx = b * 128 + tid;
    rs[tid] = d_part[2 * idx];
    rq[tid] = d_part[2 * idx + 1];
    __syncthreads();
    #pragma unroll
    for (int s = 64; s > 0; s >>= 1) {
        if (tid < s) { rs[tid] += rs[tid + s]; rq[tid] += rq[tid + s]; }
        __syncthreads();
    }
    if (tid == 0) {
        float inv = 1.0f / ((float)CINn * (float)Nn);
        float mu  = rs[0] * inv;
        float var = rq[0] * inv - mu * mu;
        d_stats[2 * b]     = mu;
        d_stats[2 * b + 1] = rsqrtf(var + EPSc);
    }
}

// ---------------- kernel 5: LN affine + residual ----------------------------
__global__ __launch_bounds__(256) void finalize_kernel(
    const float* __restrict__ x, const float* __restrict__ lw,
    const float* __restrict__ lb, float* __restrict__ out)
{
    const int per_b4 = CINn * Nn / 4;
    const int tot4   = Bn * per_b4;
    for (int i = blockIdx.x * blockDim.x + threadIdx.x; i < tot4;
         i += gridDim.x * blockDim.x) {
        int b = i / per_b4;
        int r = i - b * per_b4;
        float mu   = d_stats[2 * b];
        float rsig = d_stats[2 * b + 1];
        float4 z  = ((const float4*)d_z)[i];
        float4 xv = ((const float4*)x)[i];
        float4 w  = ((const float4*)lw)[r];
        float4 bb = ((const float4*)lb)[r];
        float4 o;
        o.x = (z.x - mu) * rsig * w.x + bb.x + xv.x;
        o.y = (z.y - mu) * rsig * w.y + bb.y + xv.y;
        o.z = (z.z - mu) * rsig * w.z + bb.z + xv.z;
        o.w = (z.w - mu) * rsig * w.w + bb.w + xv.w;
        ((float4*)out)[i] = o;
    }
}

// ---------------- launch -----------------------------------------------------
extern "C" void kernel_launch(void* const* d_in, const int* in_sizes, int n_in,
                              void* d_out, int out_size)
{
    const float* x   = (const float*)d_in[0];
    const float* Wg  = (const float*)d_in[1];
    const float* bg  = (const float*)d_in[2];
    const float* Wt  = (const float*)d_in[3];
    const float* bt  = (const float*)d_in[4];
    const float* Wp  = (const float*)d_in[5];
    const float* bp  = (const float*)d_in[6];
    const float* Wz  = (const float*)d_in[7];
    const float* bz  = (const float*)d_in[8];
    const float* lnw = (const float*)d_in[9];
    const float* lnb = (const float*)d_in[10];
    float* out = (float*)d_out;

    cudaFuncSetAttribute(attn_kernel, cudaFuncAttributeMaxDynamicSharedMemorySize,
                         ATTN_SMEM);
    cudaFuncSetAttribute(proj_mma, cudaFuncAttributeMaxDynamicSharedMemorySize,
                         PROJ_SMEM);
    cudaFuncSetAttribute(zgemm_mma, cudaFuncAttributeMaxDynamicSharedMemorySize,
                         ZG_SMEM);

    prep_w<<<128, 256>>>(Wg, Wt, Wp, Wz);
    xpose<<<dim3(128, 4, 4), 256>>>(x);
    proj_mma<<<dim3(64, 12), 256, PROJ_SMEM>>>(bg, bt, bp);
    attn_kernel<<<dim3(32, 4), 256, ATTN_SMEM>>>();
    zgemm_mma<<<dim3(64, 2, 4), 256, ZG_SMEM>>>(bz);
    stats_kernel<<<4, 128>>>();
    finalize_kernel<<<4096, 256>>>(x, lnw, lnb, out);
}